// round 3
// baseline (speedup 1.0000x reference)
#include <cuda_runtime.h>
#include <cstdint>
#include <cstddef>

// Problem constants
#define BB     8
#define MQ     512
#define NKV    2560
#define NH     16
#define HD     64
#define HID    1024
#define LW     2048
#define BH     128   // BB*NH
#define GRP    16    // head-batches per group
#define NGRP   8     // BH / GRP

// ---------------- scratch (device globals; no allocation) ----------------
__device__ float g_q   [(size_t)BH * MQ  * HD];    //  16.8 MB  [bh, m, d], pre-scaled by 1/8
__device__ float g_k   [(size_t)BH * NKV * HD];    //  83.9 MB  [bh, j, d]
__device__ float g_v   [(size_t)BH * NKV * HD];    //  83.9 MB
__device__ float g_attn[(size_t)BH * MQ  * HD];    //  16.8 MB
__device__ float g_P   [(size_t)GRP * MQ * LW];    //  67.1 MB  [bh_local*512+m, l]

// =========================================================================
// Kernel 1: C = A[R,1024] @ W[1024,1024]^T  -> head-scatter layout, scaled
// grid (1024/128, R/128), 256 threads, BM=BN=128, BK=8, 8x8 microtile
// =========================================================================
__global__ __launch_bounds__(256)
void proj_kernel(const float* __restrict__ A, const float* __restrict__ W,
                 float* __restrict__ out, int seq, float scale)
{
    __shared__ float As[8][132];
    __shared__ float Bs[8][132];
    const int tid  = threadIdx.x;
    const int row0 = blockIdx.y * 128;
    const int col0 = blockIdx.x * 128;
    const int lr = tid >> 1;
    const int lc = (tid & 1) << 2;
    const int tm = (tid >> 4) << 3;
    const int tn = (tid & 15) << 3;

    const float* Ap = A + (size_t)(row0 + lr) * HID + lc;
    const float* Wp = W + (size_t)(col0 + lr) * HID + lc;

    float acc[8][8];
#pragma unroll
    for (int i = 0; i < 8; i++)
#pragma unroll
        for (int j = 0; j < 8; j++) acc[i][j] = 0.f;

    for (int k0 = 0; k0 < HID; k0 += 8) {
        float4 a4 = *(const float4*)(Ap + k0);
        float4 w4 = *(const float4*)(Wp + k0);
        __syncthreads();
        As[lc + 0][lr] = a4.x; As[lc + 1][lr] = a4.y;
        As[lc + 2][lr] = a4.z; As[lc + 3][lr] = a4.w;
        Bs[lc + 0][lr] = w4.x; Bs[lc + 1][lr] = w4.y;
        Bs[lc + 2][lr] = w4.z; Bs[lc + 3][lr] = w4.w;
        __syncthreads();
#pragma unroll
        for (int k = 0; k < 8; k++) {
            float4 a0 = *(const float4*)&As[k][tm];
            float4 a1 = *(const float4*)&As[k][tm + 4];
            float4 b0 = *(const float4*)&Bs[k][tn];
            float4 b1 = *(const float4*)&Bs[k][tn + 4];
            float ra[8] = {a0.x,a0.y,a0.z,a0.w,a1.x,a1.y,a1.z,a1.w};
            float rb[8] = {b0.x,b0.y,b0.z,b0.w,b1.x,b1.y,b1.z,b1.w};
#pragma unroll
            for (int i = 0; i < 8; i++)
#pragma unroll
                for (int j = 0; j < 8; j++) acc[i][j] += ra[i] * rb[j];
        }
    }
    // epilogue: n = h*64 + d ; row r = b*seq + s  ->  out[((b*16+h)*seq+s)*64+d]
    const int n0 = col0 + tn;
    const int h  = n0 >> 6;
    const int d  = n0 & 63;
#pragma unroll
    for (int i = 0; i < 8; i++) {
        int r = row0 + tm + i;
        int b = r / seq;
        int s = r - b * seq;
        float* op = out + ((((size_t)(b * NH + h)) * seq + s) << 6) + d;
#pragma unroll
        for (int j = 0; j < 8; j++) op[j] = acc[i][j] * scale;
    }
}

// =========================================================================
// Kernel 2: P[8192,2048] = qheads_group[8192,64] @ pe[64,2048]
// grid (2048/128, 8192/128=64), 256 threads
// =========================================================================
__global__ __launch_bounds__(256)
void pe_kernel(const float* __restrict__ A, const float* __restrict__ Bm,
               float* __restrict__ C)
{
    __shared__ float As[8][132];
    __shared__ float Bs[8][132];
    const int tid  = threadIdx.x;
    const int row0 = blockIdx.y * 128;
    const int col0 = blockIdx.x * 128;
    const int lr = tid >> 1;
    const int lc = (tid & 1) << 2;
    const int br = tid >> 5;
    const int bc = (tid & 31) << 2;
    const int tm = (tid >> 4) << 3;
    const int tn = (tid & 15) << 3;

    float acc[8][8];
#pragma unroll
    for (int i = 0; i < 8; i++)
#pragma unroll
        for (int j = 0; j < 8; j++) acc[i][j] = 0.f;

    for (int k0 = 0; k0 < HD; k0 += 8) {
        float4 a4 = *(const float4*)(A + (size_t)(row0 + lr) * HD + k0 + lc);
        float4 b4 = *(const float4*)(Bm + (size_t)(k0 + br) * LW + col0 + bc);
        __syncthreads();
        As[lc + 0][lr] = a4.x; As[lc + 1][lr] = a4.y;
        As[lc + 2][lr] = a4.z; As[lc + 3][lr] = a4.w;
        *(float4*)&Bs[br][bc] = b4;
        __syncthreads();
#pragma unroll
        for (int k = 0; k < 8; k++) {
            float4 a0 = *(const float4*)&As[k][tm];
            float4 a1 = *(const float4*)&As[k][tm + 4];
            float4 b0 = *(const float4*)&Bs[k][tn];
            float4 b1 = *(const float4*)&Bs[k][tn + 4];
            float ra[8] = {a0.x,a0.y,a0.z,a0.w,a1.x,a1.y,a1.z,a1.w};
            float rb[8] = {b0.x,b0.y,b0.z,b0.w,b1.x,b1.y,b1.z,b1.w};
#pragma unroll
            for (int i = 0; i < 8; i++)
#pragma unroll
                for (int j = 0; j < 8; j++) acc[i][j] += ra[i] * rb[j];
        }
    }
#pragma unroll
    for (int i = 0; i < 8; i++) {
        float* cp = C + (size_t)(row0 + tm + i) * LW + col0 + tn;
        *(float4*)(cp)     = make_float4(acc[i][0], acc[i][1], acc[i][2], acc[i][3]);
        *(float4*)(cp + 4) = make_float4(acc[i][4], acc[i][5], acc[i][6], acc[i][7]);
    }
}

// =========================================================================
// Kernel 3: banded attention with precomputed positional bias (per group)
// block = (m-tile of 64 queries, bh_local). bh = bh0 + blockIdx.y.
// 256 threads: tx=tid&15 (key/dim), ty=tid>>4 (4 query rows each).
// 33 key chunks of 64 along absolute j.
// =========================================================================
#define AST 68   // smem row stride (floats): 272B, 16B-aligned

__global__ __launch_bounds__(256)
void attn_kernel(const float* __restrict__ gq, const float* __restrict__ gk,
                 const float* __restrict__ gv, const float* __restrict__ gP,
                 float* __restrict__ gout, int bh0)
{
    extern __shared__ float sm[];
    float (*sQ) [AST] = (float(*)[AST])(sm);
    float (*sKt)[AST] = (float(*)[AST])(sm + 64 * AST);
    float (*sV) [AST] = (float(*)[AST])(sm + 2 * 64 * AST);
    float (*sP) [AST] = (float(*)[AST])(sm + 3 * 64 * AST);

    const int tid = threadIdx.x;
    const int bhl = blockIdx.y;          // 0..GRP-1 (local within group)
    const int bh  = bh0 + bhl;           // global head-batch
    const int m0  = blockIdx.x << 6;
    const int tx  = tid & 15;
    const int ty  = tid >> 4;
    const int tx4 = tx << 2;
    const int i0  = ty << 2;

    // load Q tile (row-major)
    {
        int jl = tid >> 2;
        int db = (tid & 3) << 4;
        const float* qp = gq + ((((size_t)bh) * MQ + m0 + jl) << 6) + db;
#pragma unroll
        for (int u = 0; u < 4; u++)
            *(float4*)&sQ[jl][db + 4 * u] = *(const float4*)(qp + 4 * u);
    }

    float o[4][4];
#pragma unroll
    for (int a = 0; a < 4; a++)
#pragma unroll
        for (int b = 0; b < 4; b++) o[a][b] = 0.f;
    float mrow[4] = {-1e30f, -1e30f, -1e30f, -1e30f};
    float lrow[4] = {0.f, 0.f, 0.f, 0.f};
    const size_t Pbase = (((size_t)bhl) * MQ + m0) << 11;   // *2048 (local P slice)

    for (int c = 0; c <= 32; c++) {
        const int j0  = m0 + (c << 6);
        const int c64 = c << 6;
        __syncthreads();
        // load K (transposed) and V chunk
        {
            int jl = tid >> 2;
            int db = (tid & 3) << 4;
            const size_t rb = (((size_t)bh) * NKV + j0 + jl) << 6;
            const float* kp = gk + rb + db;
            const float* vp = gv + rb + db;
#pragma unroll
            for (int u = 0; u < 4; u++) {
                float4 kk = *(const float4*)(kp + 4 * u);
                int dd = db + 4 * u;
                sKt[dd + 0][jl] = kk.x; sKt[dd + 1][jl] = kk.y;
                sKt[dd + 2][jl] = kk.z; sKt[dd + 3][jl] = kk.w;
                *(float4*)&sV[jl][dd] = *(const float4*)(vp + 4 * u);
            }
        }
        __syncthreads();

        // ----- scores: s[ui][uj] = q_{i0+ui} . k_{j0+tx4+uj}
        float s[4][4];
#pragma unroll
        for (int a = 0; a < 4; a++)
#pragma unroll
            for (int b = 0; b < 4; b++) s[a][b] = 0.f;
#pragma unroll 4
        for (int d4 = 0; d4 < 64; d4 += 4) {
            float4 b0 = *(const float4*)&sKt[d4 + 0][tx4];
            float4 b1 = *(const float4*)&sKt[d4 + 1][tx4];
            float4 b2 = *(const float4*)&sKt[d4 + 2][tx4];
            float4 b3 = *(const float4*)&sKt[d4 + 3][tx4];
#pragma unroll
            for (int ui = 0; ui < 4; ui++) {
                float4 qa = *(const float4*)&sQ[i0 + ui][d4];
                s[ui][0] += qa.x * b0.x + qa.y * b1.x + qa.z * b2.x + qa.w * b3.x;
                s[ui][1] += qa.x * b0.y + qa.y * b1.y + qa.z * b2.y + qa.w * b3.y;
                s[ui][2] += qa.x * b0.z + qa.y * b1.z + qa.z * b2.z + qa.w * b3.z;
                s[ui][3] += qa.x * b0.w + qa.y * b1.w + qa.z * b2.w + qa.w * b3.w;
            }
        }

        // ----- positional bias + band mask: l = c*64 + jj - i, valid iff 0<=l<2048
#pragma unroll
        for (int ui = 0; ui < 4; ui++) {
            const int i = i0 + ui;
            const float* Pr = gP + Pbase + (((size_t)i) << 11);
#pragma unroll
            for (int uj = 0; uj < 4; uj++) {
                int l = c64 + tx4 + uj - i;
                if ((unsigned)l < (unsigned)LW) s[ui][uj] += __ldg(Pr + l);
                else                            s[ui][uj] = -1e30f;
            }
        }

        // ----- online softmax (row state replicated across the 16 tx lanes)
#pragma unroll
        for (int ui = 0; ui < 4; ui++) {
            float cm = fmaxf(fmaxf(s[ui][0], s[ui][1]), fmaxf(s[ui][2], s[ui][3]));
            cm = fmaxf(cm, __shfl_xor_sync(0xffffffffu, cm, 8));
            cm = fmaxf(cm, __shfl_xor_sync(0xffffffffu, cm, 4));
            cm = fmaxf(cm, __shfl_xor_sync(0xffffffffu, cm, 2));
            cm = fmaxf(cm, __shfl_xor_sync(0xffffffffu, cm, 1));
            float mnew = fmaxf(mrow[ui], cm);
            float corr = __expf(mrow[ui] - mnew);
            mrow[ui] = mnew;
            float ps = 0.f;
#pragma unroll
            for (int uj = 0; uj < 4; uj++) {
                float p = __expf(s[ui][uj] - mnew);
                s[ui][uj] = p;
                ps += p;
            }
            ps += __shfl_xor_sync(0xffffffffu, ps, 8);
            ps += __shfl_xor_sync(0xffffffffu, ps, 4);
            ps += __shfl_xor_sync(0xffffffffu, ps, 2);
            ps += __shfl_xor_sync(0xffffffffu, ps, 1);
            lrow[ui] = lrow[ui] * corr + ps;
            o[ui][0] *= corr; o[ui][1] *= corr; o[ui][2] *= corr; o[ui][3] *= corr;
        }

        // stage probabilities for the AV pass
#pragma unroll
        for (int ui = 0; ui < 4; ui++)
#pragma unroll
            for (int uj = 0; uj < 4; uj++)
                sP[i0 + ui][tx4 + uj] = s[ui][uj];
        __syncthreads();

        // ----- AV: o[ui][:] += p[ui][jj] * V[jj][tx4..tx4+3]
#pragma unroll 8
        for (int jj = 0; jj < 64; jj++) {
            float4 v4 = *(const float4*)&sV[jj][tx4];
            float p0 = sP[i0 + 0][jj];
            float p1 = sP[i0 + 1][jj];
            float p2 = sP[i0 + 2][jj];
            float p3 = sP[i0 + 3][jj];
            o[0][0] += p0 * v4.x; o[0][1] += p0 * v4.y; o[0][2] += p0 * v4.z; o[0][3] += p0 * v4.w;
            o[1][0] += p1 * v4.x; o[1][1] += p1 * v4.y; o[1][2] += p1 * v4.z; o[1][3] += p1 * v4.w;
            o[2][0] += p2 * v4.x; o[2][1] += p2 * v4.y; o[2][2] += p2 * v4.z; o[2][3] += p2 * v4.w;
            o[3][0] += p3 * v4.x; o[3][1] += p3 * v4.y; o[3][2] += p3 * v4.z; o[3][3] += p3 * v4.w;
        }
    }

    // epilogue
#pragma unroll
    for (int ui = 0; ui < 4; ui++) {
        float inv = 1.f / lrow[ui];
        float4 r4 = make_float4(o[ui][0] * inv, o[ui][1] * inv, o[ui][2] * inv, o[ui][3] * inv);
        *(float4*)(gout + ((((size_t)bh) * MQ + m0 + i0 + ui) << 6) + tx4) = r4;
    }
}

// =========================================================================
// Kernel 4: out = gather_heads(g_attn)[4096,1024] @ Wo^T  -> [4096,1024]
// =========================================================================
__global__ __launch_bounds__(256)
void outproj_kernel(const float* __restrict__ Ain, const float* __restrict__ W,
                    float* __restrict__ out)
{
    __shared__ float As[8][132];
    __shared__ float Bs[8][132];
    const int tid  = threadIdx.x;
    const int row0 = blockIdx.y * 128;
    const int col0 = blockIdx.x * 128;
    const int lr = tid >> 1;
    const int lc = (tid & 1) << 2;
    const int tm = (tid >> 4) << 3;
    const int tn = (tid & 15) << 3;

    const int r  = row0 + lr;
    const int b  = r >> 9;          // /512
    const int s  = r & 511;
    const float* Wp = W + (size_t)(col0 + lr) * HID + lc;

    float acc[8][8];
#pragma unroll
    for (int i = 0; i < 8; i++)
#pragma unroll
        for (int j = 0; j < 8; j++) acc[i][j] = 0.f;

    for (int k0 = 0; k0 < HID; k0 += 8) {
        const int kc = k0 + lc;
        const int h  = kc >> 6;
        const int d  = kc & 63;
        float4 a4 = *(const float4*)(Ain + ((((size_t)(b * NH + h)) * MQ + s) << 6) + d);
        float4 w4 = *(const float4*)(Wp + k0);
        __syncthreads();
        As[lc + 0][lr] = a4.x; As[lc + 1][lr] = a4.y;
        As[lc + 2][lr] = a4.z; As[lc + 3][lr] = a4.w;
        Bs[lc + 0][lr] = w4.x; Bs[lc + 1][lr] = w4.y;
        Bs[lc + 2][lr] = w4.z; Bs[lc + 3][lr] = w4.w;
        __syncthreads();
#pragma unroll
        for (int k = 0; k < 8; k++) {
            float4 a0 = *(const float4*)&As[k][tm];
            float4 a1 = *(const float4*)&As[k][tm + 4];
            float4 b0 = *(const float4*)&Bs[k][tn];
            float4 b1 = *(const float4*)&Bs[k][tn + 4];
            float ra[8] = {a0.x,a0.y,a0.z,a0.w,a1.x,a1.y,a1.z,a1.w};
            float rb[8] = {b0.x,b0.y,b0.z,b0.w,b1.x,b1.y,b1.z,b1.w};
#pragma unroll
            for (int i = 0; i < 8; i++)
#pragma unroll
                for (int j = 0; j < 8; j++) acc[i][j] += ra[i] * rb[j];
        }
    }
#pragma unroll
    for (int i = 0; i < 8; i++) {
        float* op = out + (size_t)(row0 + tm + i) * HID + col0 + tn;
        *(float4*)(op)     = make_float4(acc[i][0], acc[i][1], acc[i][2], acc[i][3]);
        *(float4*)(op + 4) = make_float4(acc[i][4], acc[i][5], acc[i][6], acc[i][7]);
    }
}

// =========================================================================
// host launcher
// =========================================================================
extern "C" void kernel_launch(void* const* d_in, const int* in_sizes, int n_in,
                              void* d_out, int out_size)
{
    const float* query  = (const float*)d_in[0];
    const float* key    = (const float*)d_in[1];
    const float* value  = (const float*)d_in[2];
    const float* key_pe = (const float*)d_in[3];
    const float* Wq     = (const float*)d_in[4];
    const float* Wk     = (const float*)d_in[5];
    const float* Wv     = (const float*)d_in[6];
    const float* Wo     = (const float*)d_in[7];
    float* out = (float*)d_out;

    float *pq, *pk, *pv, *pa, *pP;
    cudaGetSymbolAddress((void**)&pq, g_q);
    cudaGetSymbolAddress((void**)&pk, g_k);
    cudaGetSymbolAddress((void**)&pv, g_v);
    cudaGetSymbolAddress((void**)&pa, g_attn);
    cudaGetSymbolAddress((void**)&pP, g_P);

    // Q/K/V projections (1/sqrt(HEAD)=0.125 folded into q)
    proj_kernel<<<dim3(8,  32), 256>>>(query, Wq, pq, MQ,  0.125f);
    proj_kernel<<<dim3(8, 160), 256>>>(key,   Wk, pk, NKV, 1.0f);
    proj_kernel<<<dim3(8, 160), 256>>>(value, Wv, pv, NKV, 1.0f);

    // grouped: pos-bias GEMM then banded attention, 16 head-batches at a time
    const int smem = 4 * 64 * AST * (int)sizeof(float);   // 69632 B
    (void)cudaFuncSetAttribute(attn_kernel, cudaFuncAttributeMaxDynamicSharedMemorySize, smem);
    for (int g = 0; g < NGRP; g++) {
        const float* qg = pq + (size_t)g * GRP * MQ * HD;
        pe_kernel<<<dim3(16, 64), 256>>>(qg, key_pe, pP);
        attn_kernel<<<dim3(8, GRP), 256, smem>>>(pq, pk, pv, pP, pa, g * GRP);
    }

    // output projection
    outproj_kernel<<<dim3(8, 32), 256>>>(pa, Wo, out);
}

// round 7
// speedup vs baseline: 1.3682x; 1.3682x over previous
#include <cuda_runtime.h>
#include <cuda_bf16.h>
#include <cstdint>
#include <cstddef>

// Problem constants
#define BB     8
#define MQ     512
#define NKV    2560
#define NH     16
#define HD     64
#define HID    1024
#define LW     2048
#define BH     128   // BB*NH
#define GRP    16    // head-batches per group (for P buffer)
#define NGRP   8     // BH / GRP

// ---------------- scratch (device globals; no allocation) ----------------
// Total: 268.5 MB — identical footprint to the R3 kernel that PASSED.
__device__ float g_q   [(size_t)BH * MQ  * HD];      //  16.8 MB  [bh, m, d], pre-scaled by 1/8
__device__ float g_k   [(size_t)BH * NKV * HD];      //  83.9 MB  [bh, j, d]
__device__ float g_v   [(size_t)BH * NKV * HD];      //  83.9 MB
__device__ float g_attn[(size_t)BB * MQ  * HID];     //  16.8 MB  [b*512+m, h*64+d] (gathered)
__device__ float g_P   [(size_t)GRP * MQ * LW];      //  67.1 MB  [bh_local*512+m, l]

// ======================= helpers =============================
__device__ __forceinline__ uint32_t smem_u32(const void* p) {
    uint32_t a;
    asm("{ .reg .u64 t; cvta.to.shared.u64 t, %1; cvt.u32.u64 %0, t; }" : "=r"(a) : "l"(p));
    return a;
}
__device__ __forceinline__ void ldsm_x4(uint32_t& r0, uint32_t& r1, uint32_t& r2, uint32_t& r3,
                                        uint32_t addr) {
    asm volatile("ldmatrix.sync.aligned.m8n8.x4.shared.b16 {%0,%1,%2,%3}, [%4];"
                 : "=r"(r0), "=r"(r1), "=r"(r2), "=r"(r3) : "r"(addr));
}
__device__ __forceinline__ void mma16816(float& d0, float& d1, float& d2, float& d3,
                                         uint32_t a0, uint32_t a1, uint32_t a2, uint32_t a3,
                                         uint32_t b0, uint32_t b1) {
    asm volatile("mma.sync.aligned.m16n8k16.row.col.f32.bf16.bf16.f32 "
                 "{%0,%1,%2,%3}, {%4,%5,%6,%7}, {%8,%9}, {%0,%1,%2,%3};"
                 : "+f"(d0), "+f"(d1), "+f"(d2), "+f"(d3)
                 : "r"(a0), "r"(a1), "r"(a2), "r"(a3), "r"(b0), "r"(b1));
}

// =========================================================================
// mma.sync split-bf16 GEMM:  C[rows,1024] = A[rows,1024] @ B[1024,1024]^T
// fp32 inputs split in-kernel to bf16 hi/lo; 3 MMA passes (hh + hl + lh).
// Block 64(M) x 128(N), 256 thr, warp grid 4(m) x 2(n), warp tile 16x64.
// K-slab 32 (2 ksteps of 16), single smem buffer, 2 CTAs/SM for overlap.
// mode 0: C row-major. mode 1: head-scatter out[((b*16+h)*seq+s)*64+d].
// grid: (8, rows/64).
// =========================================================================
#define KSLAB   32
#define SROW    40              // bf16 row stride (80 bytes, 16B-aligned)
#define SA_H    0               // byte offsets in shared
#define SA_L    (64  * 80)      //  5120
#define SB_H    (2 * 64 * 80)   // 10240
#define SB_L    (SB_H + 128 * 80)  // 20480
#define SMEMSZ  (SB_L + 128 * 80)  // 30720 bytes

__global__ __launch_bounds__(256, 2)
void tc_gemm_mma(const float* __restrict__ A, const float* __restrict__ B,
                 float* __restrict__ out, int seq, float scale, int mode)
{
    __shared__ __align__(16) uint8_t smem[SMEMSZ];
    const uint32_t sb = smem_u32(smem);

    const int tid  = threadIdx.x;
    const int lane = tid & 31;
    const int wid  = tid >> 5;
    const int wm   = (wid & 3) << 4;     // warp m offset 0..48
    const int wn   = (wid >> 2) << 6;    // warp n offset 0 or 64
    const int row0 = blockIdx.y << 6;    // 64 rows per block
    const int col0 = blockIdx.x << 7;    // 128 cols per block

    float acc[8][4];
#pragma unroll
    for (int j = 0; j < 8; j++)
#pragma unroll
        for (int q = 0; q < 4; q++) acc[j][q] = 0.f;

    // ldmatrix lane addressing (within a 16x16 bf16 tile at row r0, col-byte cb)
    const int lrow = lane & 15;
    const int lcol = (lane >> 4) << 4;   // 0 or 16 bytes

    for (int ks = 0; ks < HID; ks += KSLAB) {
        __syncthreads();
        // ---- stage + split A (64x32) ----
#pragma unroll
        for (int u = 0; u < 2; u++) {
            int v = (u << 8) + tid;           // 0..511
            int r = v >> 3;
            int c4 = (v & 7) << 2;
            float4 x = *(const float4*)(A + (size_t)(row0 + r) * HID + ks + c4);
            __nv_bfloat16 h0 = __float2bfloat16_rn(x.x), h1 = __float2bfloat16_rn(x.y);
            __nv_bfloat16 h2 = __float2bfloat16_rn(x.z), h3 = __float2bfloat16_rn(x.w);
            __nv_bfloat16 l0 = __float2bfloat16_rn(x.x - __bfloat162float(h0));
            __nv_bfloat16 l1 = __float2bfloat16_rn(x.y - __bfloat162float(h1));
            __nv_bfloat16 l2 = __float2bfloat16_rn(x.z - __bfloat162float(h2));
            __nv_bfloat16 l3 = __float2bfloat16_rn(x.w - __bfloat162float(h3));
            __nv_bfloat162 th0(h0, h1), th1(h2, h3), tl0(l0, l1), tl1(l2, l3);
            uint32_t off = r * 80 + (c4 << 1);
            *(uint2*)(smem + SA_H + off) = make_uint2(*(uint32_t*)&th0, *(uint32_t*)&th1);
            *(uint2*)(smem + SA_L + off) = make_uint2(*(uint32_t*)&tl0, *(uint32_t*)&tl1);
        }
        // ---- stage + split B (128x32) ----
#pragma unroll
        for (int u = 0; u < 4; u++) {
            int v = (u << 8) + tid;           // 0..1023
            int r = v >> 3;
            int c4 = (v & 7) << 2;
            float4 x = *(const float4*)(B + (size_t)(col0 + r) * HID + ks + c4);
            __nv_bfloat16 h0 = __float2bfloat16_rn(x.x), h1 = __float2bfloat16_rn(x.y);
            __nv_bfloat16 h2 = __float2bfloat16_rn(x.z), h3 = __float2bfloat16_rn(x.w);
            __nv_bfloat16 l0 = __float2bfloat16_rn(x.x - __bfloat162float(h0));
            __nv_bfloat16 l1 = __float2bfloat16_rn(x.y - __bfloat162float(h1));
            __nv_bfloat16 l2 = __float2bfloat16_rn(x.z - __bfloat162float(h2));
            __nv_bfloat16 l3 = __float2bfloat16_rn(x.w - __bfloat162float(h3));
            __nv_bfloat162 th0(h0, h1), th1(h2, h3), tl0(l0, l1), tl1(l2, l3);
            uint32_t off = r * 80 + (c4 << 1);
            *(uint2*)(smem + SB_H + off) = make_uint2(*(uint32_t*)&th0, *(uint32_t*)&th1);
            *(uint2*)(smem + SB_L + off) = make_uint2(*(uint32_t*)&tl0, *(uint32_t*)&tl1);
        }
        __syncthreads();

        // ---- 2 ksteps of 16 ----
#pragma unroll
        for (int kk = 0; kk < 2; kk++) {
            const uint32_t kb = (kk << 5);  // kstep byte offset = kk*16*2
            // A fragments hi/lo (16x16 tile at (wm, kstep))
            uint32_t ah0, ah1, ah2, ah3, al0, al1, al2, al3;
            {
                uint32_t ar = sb + SA_H + (wm + lrow) * 80 + kb + lcol;
                ldsm_x4(ah0, ah1, ah2, ah3, ar);
                ldsm_x4(al0, al1, al2, al3, ar + (SA_L - SA_H));
            }
            // B hi fragments: 4 pairs (16 n-rows each)
            uint32_t bh[8][2];
#pragma unroll
            for (int p = 0; p < 4; p++) {
                uint32_t br = sb + SB_H + (wn + (p << 4) + lrow) * 80 + kb + lcol;
                uint32_t r0, r1, r2, r3;
                ldsm_x4(r0, r1, r2, r3, br);
                bh[2*p][0] = r0; bh[2*p][1] = r2;
                bh[2*p+1][0] = r1; bh[2*p+1][1] = r3;
            }
            // hh + lh
#pragma unroll
            for (int j = 0; j < 8; j++) {
                mma16816(acc[j][0], acc[j][1], acc[j][2], acc[j][3],
                         ah0, ah1, ah2, ah3, bh[j][0], bh[j][1]);
                mma16816(acc[j][0], acc[j][1], acc[j][2], acc[j][3],
                         al0, al1, al2, al3, bh[j][0], bh[j][1]);
            }
            // B lo fragments, hl
#pragma unroll
            for (int p = 0; p < 4; p++) {
                uint32_t br = sb + SB_L + (wn + (p << 4) + lrow) * 80 + kb + lcol;
                uint32_t r0, r1, r2, r3;
                ldsm_x4(r0, r1, r2, r3, br);
                bh[2*p][0] = r0; bh[2*p][1] = r2;
                bh[2*p+1][0] = r1; bh[2*p+1][1] = r3;
            }
#pragma unroll
            for (int j = 0; j < 8; j++) {
                mma16816(acc[j][0], acc[j][1], acc[j][2], acc[j][3],
                         ah0, ah1, ah2, ah3, bh[j][0], bh[j][1]);
            }
        }
    }

    // ---- epilogue: direct stores from accumulators ----
    const int r_lo = row0 + wm + (lane >> 2);
    const int c_base = col0 + wn + ((lane & 3) << 1);
#pragma unroll
    for (int j = 0; j < 8; j++) {
        int col = c_base + (j << 3);
#pragma unroll
        for (int half = 0; half < 2; half++) {
            int r = r_lo + (half << 3);
            float v0 = acc[j][half * 2 + 0] * scale;
            float v1 = acc[j][half * 2 + 1] * scale;
            if (mode == 1) {
                int b = r / seq;
                int s = r - b * seq;
                int h = col >> 6;
                int d = col & 63;
                float* op = out + (((size_t)(b * NH + h)) * seq + s) * 64 + d;
                op[0] = v0; op[1] = v1;
            } else {
                float* op = out + (size_t)r * HID + col;
                op[0] = v0; op[1] = v1;
            }
        }
    }
}

// =========================================================================
// pe_kernel: P[8192,2048] = qheads_group[8192,64] @ pe[64,2048]   (fp32 SIMT)
// =========================================================================
__global__ __launch_bounds__(256)
void pe_kernel(const float* __restrict__ A, const float* __restrict__ Bm,
               float* __restrict__ C)
{
    __shared__ float As[8][132];
    __shared__ float Bs[8][132];
    const int tid  = threadIdx.x;
    const int row0 = blockIdx.y * 128;
    const int col0 = blockIdx.x * 128;
    const int lr = tid >> 1;
    const int lc = (tid & 1) << 2;
    const int br = tid >> 5;
    const int bc = (tid & 31) << 2;
    const int tm = (tid >> 4) << 3;
    const int tn = (tid & 15) << 3;

    float acc[8][8];
#pragma unroll
    for (int i = 0; i < 8; i++)
#pragma unroll
        for (int j = 0; j < 8; j++) acc[i][j] = 0.f;

    for (int k0 = 0; k0 < HD; k0 += 8) {
        float4 a4 = *(const float4*)(A + (size_t)(row0 + lr) * HD + k0 + lc);
        float4 b4 = *(const float4*)(Bm + (size_t)(k0 + br) * LW + col0 + bc);
        __syncthreads();
        As[lc + 0][lr] = a4.x; As[lc + 1][lr] = a4.y;
        As[lc + 2][lr] = a4.z; As[lc + 3][lr] = a4.w;
        *(float4*)&Bs[br][bc] = b4;
        __syncthreads();
#pragma unroll
        for (int k = 0; k < 8; k++) {
            float4 a0 = *(const float4*)&As[k][tm];
            float4 a1 = *(const float4*)&As[k][tm + 4];
            float4 b0 = *(const float4*)&Bs[k][tn];
            float4 b1 = *(const float4*)&Bs[k][tn + 4];
            float ra[8] = {a0.x,a0.y,a0.z,a0.w,a1.x,a1.y,a1.z,a1.w};
            float rb[8] = {b0.x,b0.y,b0.z,b0.w,b1.x,b1.y,b1.z,b1.w};
#pragma unroll
            for (int i = 0; i < 8; i++)
#pragma unroll
                for (int j = 0; j < 8; j++) acc[i][j] += ra[i] * rb[j];
        }
    }
#pragma unroll
    for (int i = 0; i < 8; i++) {
        float* cp = C + (size_t)(row0 + tm + i) * LW + col0 + tn;
        *(float4*)(cp)     = make_float4(acc[i][0], acc[i][1], acc[i][2], acc[i][3]);
        *(float4*)(cp + 4) = make_float4(acc[i][4], acc[i][5], acc[i][6], acc[i][7]);
    }
}

// =========================================================================
// attn_kernel: banded attention with precomputed positional bias (per group)
// writes GATHERED output layout: [b*512+m, h*64+d]
// =========================================================================
#define AST 68

__global__ __launch_bounds__(256)
void attn_kernel(const float* __restrict__ gq, const float* __restrict__ gk,
                 const float* __restrict__ gv, const float* __restrict__ gP,
                 float* __restrict__ gout, int bh0)
{
    extern __shared__ float sm[];
    float (*sQ) [AST] = (float(*)[AST])(sm);
    float (*sKt)[AST] = (float(*)[AST])(sm + 64 * AST);
    float (*sV) [AST] = (float(*)[AST])(sm + 2 * 64 * AST);
    float (*sP) [AST] = (float(*)[AST])(sm + 3 * 64 * AST);

    const int tid = threadIdx.x;
    const int bhl = blockIdx.y;
    const int bh  = bh0 + bhl;
    const int m0  = blockIdx.x << 6;
    const int tx  = tid & 15;
    const int ty  = tid >> 4;
    const int tx4 = tx << 2;
    const int i0  = ty << 2;

    {
        int jl = tid >> 2;
        int db = (tid & 3) << 4;
        const float* qp = gq + ((((size_t)bh) * MQ + m0 + jl) << 6) + db;
#pragma unroll
        for (int u = 0; u < 4; u++)
            *(float4*)&sQ[jl][db + 4 * u] = *(const float4*)(qp + 4 * u);
    }

    float o[4][4];
#pragma unroll
    for (int a = 0; a < 4; a++)
#pragma unroll
        for (int b = 0; b < 4; b++) o[a][b] = 0.f;
    float mrow[4] = {-1e30f, -1e30f, -1e30f, -1e30f};
    float lrow[4] = {0.f, 0.f, 0.f, 0.f};
    const size_t Pbase = (((size_t)bhl) * MQ + m0) << 11;

    for (int c = 0; c <= 32; c++) {
        const int j0  = m0 + (c << 6);
        const int c64 = c << 6;
        __syncthreads();
        {
            int jl = tid >> 2;
            int db = (tid & 3) << 4;
            const size_t rb = (((size_t)bh) * NKV + j0 + jl) << 6;
            const float* kp = gk + rb + db;
            const float* vp = gv + rb + db;
#pragma unroll
            for (int u = 0; u < 4; u++) {
                float4 kk = *(const float4*)(kp + 4 * u);
                int dd = db + 4 * u;
                sKt[dd + 0][jl] = kk.x; sKt[dd + 1][jl] = kk.y;
                sKt[dd + 2][jl] = kk.z; sKt[dd + 3][jl] = kk.w;
                *(float4*)&sV[jl][dd] = *(const float4*)(vp + 4 * u);
            }
        }
        __syncthreads();

        float s[4][4];
#pragma unroll
        for (int a = 0; a < 4; a++)
#pragma unroll
            for (int b = 0; b < 4; b++) s[a][b] = 0.f;
#pragma unroll 4
        for (int d4 = 0; d4 < 64; d4 += 4) {
            float4 b0 = *(const float4*)&sKt[d4 + 0][tx4];
            float4 b1 = *(const float4*)&sKt[d4 + 1][tx4];
            float4 b2 = *(const float4*)&sKt[d4 + 2][tx4];
            float4 b3 = *(const float4*)&sKt[d4 + 3][tx4];
#pragma unroll
            for (int ui = 0; ui < 4; ui++) {
                float4 qa = *(const float4*)&sQ[i0 + ui][d4];
                s[ui][0] += qa.x * b0.x + qa.y * b1.x + qa.z * b2.x + qa.w * b3.x;
                s[ui][1] += qa.x * b0.y + qa.y * b1.y + qa.z * b2.y + qa.w * b3.y;
                s[ui][2] += qa.x * b0.z + qa.y * b1.z + qa.z * b2.z + qa.w * b3.z;
                s[ui][3] += qa.x * b0.w + qa.y * b1.w + qa.z * b2.w + qa.w * b3.w;
            }
        }

#pragma unroll
        for (int ui = 0; ui < 4; ui++) {
            const int i = i0 + ui;
            const float* Pr = gP + Pbase + (((size_t)i) << 11);
#pragma unroll
            for (int uj = 0; uj < 4; uj++) {
                int l = c64 + tx4 + uj - i;
                if ((unsigned)l < (unsigned)LW) s[ui][uj] += __ldg(Pr + l);
                else                            s[ui][uj] = -1e30f;
            }
        }

#pragma unroll
        for (int ui = 0; ui < 4; ui++) {
            float cm = fmaxf(fmaxf(s[ui][0], s[ui][1]), fmaxf(s[ui][2], s[ui][3]));
            cm = fmaxf(cm, __shfl_xor_sync(0xffffffffu, cm, 8));
            cm = fmaxf(cm, __shfl_xor_sync(0xffffffffu, cm, 4));
            cm = fmaxf(cm, __shfl_xor_sync(0xffffffffu, cm, 2));
            cm = fmaxf(cm, __shfl_xor_sync(0xffffffffu, cm, 1));
            float mnew = fmaxf(mrow[ui], cm);
            float corr = __expf(mrow[ui] - mnew);
            mrow[ui] = mnew;
            float ps = 0.f;
#pragma unroll
            for (int uj = 0; uj < 4; uj++) {
                float p = __expf(s[ui][uj] - mnew);
                s[ui][uj] = p;
                ps += p;
            }
            ps += __shfl_xor_sync(0xffffffffu, ps, 8);
            ps += __shfl_xor_sync(0xffffffffu, ps, 4);
            ps += __shfl_xor_sync(0xffffffffu, ps, 2);
            ps += __shfl_xor_sync(0xffffffffu, ps, 1);
            lrow[ui] = lrow[ui] * corr + ps;
            o[ui][0] *= corr; o[ui][1] *= corr; o[ui][2] *= corr; o[ui][3] *= corr;
        }

#pragma unroll
        for (int ui = 0; ui < 4; ui++)
#pragma unroll
            for (int uj = 0; uj < 4; uj++)
                sP[i0 + ui][tx4 + uj] = s[ui][uj];
        __syncthreads();

#pragma unroll 8
        for (int jj = 0; jj < 64; jj++) {
            float4 v4 = *(const float4*)&sV[jj][tx4];
            float p0 = sP[i0 + 0][jj];
            float p1 = sP[i0 + 1][jj];
            float p2 = sP[i0 + 2][jj];
            float p3 = sP[i0 + 3][jj];
            o[0][0] += p0 * v4.x; o[0][1] += p0 * v4.y; o[0][2] += p0 * v4.z; o[0][3] += p0 * v4.w;
            o[1][0] += p1 * v4.x; o[1][1] += p1 * v4.y; o[1][2] += p1 * v4.z; o[1][3] += p1 * v4.w;
            o[2][0] += p2 * v4.x; o[2][1] += p2 * v4.y; o[2][2] += p2 * v4.z; o[2][3] += p2 * v4.w;
            o[3][0] += p3 * v4.x; o[3][1] += p3 * v4.y; o[3][2] += p3 * v4.z; o[3][3] += p3 * v4.w;
        }
    }

    // epilogue (gathered layout: [b*512+m, h*64+d])
    const int bb = bh >> 4;
    const int h  = bh & 15;
#pragma unroll
    for (int ui = 0; ui < 4; ui++) {
        float inv = 1.f / lrow[ui];
        float4 r4 = make_float4(o[ui][0] * inv, o[ui][1] * inv, o[ui][2] * inv, o[ui][3] * inv);
        size_t row = (size_t)bb * MQ + m0 + i0 + ui;
        *(float4*)(gout + row * HID + (h << 6) + tx4) = r4;
    }
}

// =========================================================================
// host launcher
// =========================================================================
extern "C" void kernel_launch(void* const* d_in, const int* in_sizes, int n_in,
                              void* d_out, int out_size)
{
    const float* query  = (const float*)d_in[0];
    const float* key    = (const float*)d_in[1];
    const float* value  = (const float*)d_in[2];
    const float* key_pe = (const float*)d_in[3];
    const float* Wq     = (const float*)d_in[4];
    const float* Wk     = (const float*)d_in[5];
    const float* Wv     = (const float*)d_in[6];
    const float* Wo     = (const float*)d_in[7];
    float* out = (float*)d_out;

    float *pq, *pk, *pv, *pa, *pP;
    cudaGetSymbolAddress((void**)&pq, g_q);
    cudaGetSymbolAddress((void**)&pk, g_k);
    cudaGetSymbolAddress((void**)&pv, g_v);
    cudaGetSymbolAddress((void**)&pa, g_attn);
    cudaGetSymbolAddress((void**)&pP, g_P);

    // ---- projections via mma.sync split-bf16 (1/8 scale folded into Q) ----
    tc_gemm_mma<<<dim3(8, BB * MQ  / 64), 256>>>(query, Wq, pq, MQ,  0.125f, 1);
    tc_gemm_mma<<<dim3(8, BB * NKV / 64), 256>>>(key,   Wk, pk, NKV, 1.0f,   1);
    tc_gemm_mma<<<dim3(8, BB * NKV / 64), 256>>>(value, Wv, pv, NKV, 1.0f,   1);

    // ---- grouped: pos-bias GEMM + banded attention ----
    const int smem = 4 * 64 * AST * (int)sizeof(float);
    (void)cudaFuncSetAttribute(attn_kernel, cudaFuncAttributeMaxDynamicSharedMemorySize, smem);
    for (int g = 0; g < NGRP; g++) {
        const float* qg = pq + (size_t)g * GRP * MQ * HD;
        pe_kernel<<<dim3(16, 64), 256>>>(qg, key_pe, pP);
        attn_kernel<<<dim3(8, GRP), 256, smem>>>(pq, pk, pv, pP, pa, g * GRP);
    }

    // ---- output projection (gathered input, row-major output) ----
    tc_gemm_mma<<<dim3(8, BB * MQ / 64), 256>>>(pa, Wo, out, MQ, 1.0f, 0);
}

// round 11
// speedup vs baseline: 1.3979x; 1.0217x over previous
#include <cuda_runtime.h>
#include <cuda_bf16.h>
#include <cstdint>
#include <cstddef>

// Problem constants
#define BB     8
#define MQ     512
#define NKV    2560
#define NH     16
#define HD     64
#define HID    1024
#define LW     2048
#define BH     128   // BB*NH
#define GRP    16    // head-batches per group (for P buffer)
#define NGRP   8     // BH / GRP

// ---------------- scratch (device globals; no allocation) ----------------
__device__ float g_q   [(size_t)BH * MQ  * HD];      //  16.8 MB  [bh, m, d], pre-scaled by 1/8
__device__ float g_k   [(size_t)BH * NKV * HD];      //  83.9 MB  [bh, j, d]
__device__ float g_v   [(size_t)BH * NKV * HD];      //  83.9 MB
__device__ float g_attn[(size_t)BB * MQ  * HID];     //  16.8 MB  [b*512+m, h*64+d] (gathered)
__device__ float g_P   [(size_t)GRP * MQ * LW];      //  67.1 MB  [bh_local*512+m, l]
// pre-split bf16 B-operand buffers
__device__ __nv_bfloat16 g_wh [(size_t)HID * HID];   //   2 MB (weight hi, reused per projection)
__device__ __nv_bfloat16 g_wl [(size_t)HID * HID];   //   2 MB (weight lo)
__device__ __nv_bfloat16 g_peh[(size_t)LW * HD];     // 256 KB (pe^T hi: [l, d])
__device__ __nv_bfloat16 g_pel[(size_t)LW * HD];     // 256 KB (pe^T lo)

// ======================= helpers =============================
__device__ __forceinline__ uint32_t smem_u32(const void* p) {
    uint32_t a;
    asm("{ .reg .u64 t; cvta.to.shared.u64 t, %1; cvt.u32.u64 %0, t; }" : "=r"(a) : "l"(p));
    return a;
}
__device__ __forceinline__ void ldsm_x4(uint32_t& r0, uint32_t& r1, uint32_t& r2, uint32_t& r3,
                                        uint32_t addr) {
    asm volatile("ldmatrix.sync.aligned.m8n8.x4.shared.b16 {%0,%1,%2,%3}, [%4];"
                 : "=r"(r0), "=r"(r1), "=r"(r2), "=r"(r3) : "r"(addr));
}
__device__ __forceinline__ void mma16816(float& d0, float& d1, float& d2, float& d3,
                                         uint32_t a0, uint32_t a1, uint32_t a2, uint32_t a3,
                                         uint32_t b0, uint32_t b1) {
    asm volatile("mma.sync.aligned.m16n8k16.row.col.f32.bf16.bf16.f32 "
                 "{%0,%1,%2,%3}, {%4,%5,%6,%7}, {%8,%9}, {%0,%1,%2,%3};"
                 : "+f"(d0), "+f"(d1), "+f"(d2), "+f"(d3)
                 : "r"(a0), "r"(a1), "r"(a2), "r"(a3), "r"(b0), "r"(b1));
}

// =========================================================================
// split_w: fp32 [n] -> bf16 hi/lo (elementwise, float4)
// =========================================================================
__global__ __launch_bounds__(256)
void split_w(const float* __restrict__ in, __nv_bfloat16* __restrict__ hi,
             __nv_bfloat16* __restrict__ lo, int n4)
{
    int i = blockIdx.x * 256 + threadIdx.x;
    if (i >= n4) return;
    float4 x = ((const float4*)in)[i];
    __nv_bfloat16 h0 = __float2bfloat16_rn(x.x), h1 = __float2bfloat16_rn(x.y);
    __nv_bfloat16 h2 = __float2bfloat16_rn(x.z), h3 = __float2bfloat16_rn(x.w);
    __nv_bfloat16 l0 = __float2bfloat16_rn(x.x - __bfloat162float(h0));
    __nv_bfloat16 l1 = __float2bfloat16_rn(x.y - __bfloat162float(h1));
    __nv_bfloat16 l2 = __float2bfloat16_rn(x.z - __bfloat162float(h2));
    __nv_bfloat16 l3 = __float2bfloat16_rn(x.w - __bfloat162float(h3));
    __nv_bfloat162 th0(h0, h1), th1(h2, h3), tl0(l0, l1), tl1(l2, l3);
    ((uint2*)hi)[i] = make_uint2(*(uint32_t*)&th0, *(uint32_t*)&th1);
    ((uint2*)lo)[i] = make_uint2(*(uint32_t*)&tl0, *(uint32_t*)&tl1);
}

// =========================================================================
// split_peT: pe[d, l] (64 x 2048) -> peT hi/lo [l, d] (2048 x 64)
// =========================================================================
__global__ __launch_bounds__(256)
void split_peT(const float* __restrict__ pe, __nv_bfloat16* __restrict__ hi,
               __nv_bfloat16* __restrict__ lo)
{
    int idx = blockIdx.x * 256 + threadIdx.x;   // 0 .. 131071
    if (idx >= LW * HD) return;
    int d = idx & 63;
    int l = idx >> 6;
    float x = pe[(size_t)d * LW + l];
    __nv_bfloat16 h = __float2bfloat16_rn(x);
    __nv_bfloat16 ll = __float2bfloat16_rn(x - __bfloat162float(h));
    hi[idx] = h;
    lo[idx] = ll;
}

// =========================================================================
// mma.sync split-bf16 GEMM:  C[rows, N] = A[rows, K] @ B[N, K]^T
// A fp32 (split in-kernel); B pre-split bf16 hi/lo (K-contiguous rows).
// Block 64(M) x 128(N), 256 thr, warp grid 4(m) x 2(n), warp tile 16x64.
// K-slab 32 (2 ksteps of 16), single smem buffer, 2 CTAs/SM for overlap.
// mode 0: C row-major with stride ldc. mode 1: head-scatter.
// grid: (N/128, rows/64).
// =========================================================================
#define SA_H    0                   // byte offsets in shared
#define SA_L    (64  * 80)          //  5120
#define SB_H    (2 * 64 * 80)       // 10240
#define SB_L    (SB_H + 128 * 80)   // 20480
#define SMEMSZ  (SB_L + 128 * 80)   // 30720 bytes

__global__ __launch_bounds__(256, 2)
void tc_gemm_mma(const float* __restrict__ A,
                 const __nv_bfloat16* __restrict__ Bh, const __nv_bfloat16* __restrict__ Bl,
                 float* __restrict__ out, int lda, int K, int ldc,
                 int seq, float scale, int mode)
{
    __shared__ __align__(16) uint8_t smem[SMEMSZ];
    const uint32_t sb = smem_u32(smem);

    const int tid  = threadIdx.x;
    const int lane = tid & 31;
    const int wid  = tid >> 5;
    const int wm   = (wid & 3) << 4;     // warp m offset 0..48
    const int wn   = (wid >> 2) << 6;    // warp n offset 0 or 64
    const int row0 = blockIdx.y << 6;    // 64 rows per block
    const int col0 = blockIdx.x << 7;    // 128 cols per block

    float acc[8][4];
#pragma unroll
    for (int j = 0; j < 8; j++)
#pragma unroll
        for (int q = 0; q < 4; q++) acc[j][q] = 0.f;

    const int lrow = lane & 15;
    const int lcol = (lane >> 4) << 4;   // 0 or 16 bytes

    for (int ks = 0; ks < K; ks += 32) {
        __syncthreads();
        // ---- stage + split A (64x32 fp32) ----
#pragma unroll
        for (int u = 0; u < 2; u++) {
            int v = (u << 8) + tid;           // 0..511
            int r = v >> 3;
            int c4 = (v & 7) << 2;
            float4 x = *(const float4*)(A + (size_t)(row0 + r) * lda + ks + c4);
            __nv_bfloat16 h0 = __float2bfloat16_rn(x.x), h1 = __float2bfloat16_rn(x.y);
            __nv_bfloat16 h2 = __float2bfloat16_rn(x.z), h3 = __float2bfloat16_rn(x.w);
            __nv_bfloat16 l0 = __float2bfloat16_rn(x.x - __bfloat162float(h0));
            __nv_bfloat16 l1 = __float2bfloat16_rn(x.y - __bfloat162float(h1));
            __nv_bfloat16 l2 = __float2bfloat16_rn(x.z - __bfloat162float(h2));
            __nv_bfloat16 l3 = __float2bfloat16_rn(x.w - __bfloat162float(h3));
            __nv_bfloat162 th0(h0, h1), th1(h2, h3), tl0(l0, l1), tl1(l2, l3);
            uint32_t off = r * 80 + (c4 << 1);
            *(uint2*)(smem + SA_H + off) = make_uint2(*(uint32_t*)&th0, *(uint32_t*)&th1);
            *(uint2*)(smem + SA_L + off) = make_uint2(*(uint32_t*)&tl0, *(uint32_t*)&tl1);
        }
        // ---- stage B (128x32 bf16 hi + lo, pure copy) ----
#pragma unroll
        for (int u = 0; u < 2; u++) {
            int v = (u << 8) + tid;           // 0..511
            int r = v >> 2;                   // 0..127
            int cb = (v & 3) << 3;            // bf16 col 0,8,16,24
            uint32_t off = r * 80 + (cb << 1);
            *(uint4*)(smem + SB_H + off) = *(const uint4*)(Bh + (size_t)(col0 + r) * K + ks + cb);
            *(uint4*)(smem + SB_L + off) = *(const uint4*)(Bl + (size_t)(col0 + r) * K + ks + cb);
        }
        __syncthreads();

        // ---- 2 ksteps of 16 ----
#pragma unroll
        for (int kk = 0; kk < 2; kk++) {
            const uint32_t kb = (kk << 5);
            uint32_t ah0, ah1, ah2, ah3, al0, al1, al2, al3;
            {
                uint32_t ar = sb + SA_H + (wm + lrow) * 80 + kb + lcol;
                ldsm_x4(ah0, ah1, ah2, ah3, ar);
                ldsm_x4(al0, al1, al2, al3, ar + (SA_L - SA_H));
            }
            uint32_t bh[8][2];
#pragma unroll
            for (int p = 0; p < 4; p++) {
                uint32_t br = sb + SB_H + (wn + (p << 4) + lrow) * 80 + kb + lcol;
                uint32_t r0, r1, r2, r3;
                ldsm_x4(r0, r1, r2, r3, br);
                bh[2*p][0] = r0; bh[2*p][1] = r2;
                bh[2*p+1][0] = r1; bh[2*p+1][1] = r3;
            }
#pragma unroll
            for (int j = 0; j < 8; j++) {
                mma16816(acc[j][0], acc[j][1], acc[j][2], acc[j][3],
                         ah0, ah1, ah2, ah3, bh[j][0], bh[j][1]);
                mma16816(acc[j][0], acc[j][1], acc[j][2], acc[j][3],
                         al0, al1, al2, al3, bh[j][0], bh[j][1]);
            }
#pragma unroll
            for (int p = 0; p < 4; p++) {
                uint32_t br = sb + SB_L + (wn + (p << 4) + lrow) * 80 + kb + lcol;
                uint32_t r0, r1, r2, r3;
                ldsm_x4(r0, r1, r2, r3, br);
                bh[2*p][0] = r0; bh[2*p][1] = r2;
                bh[2*p+1][0] = r1; bh[2*p+1][1] = r3;
            }
#pragma unroll
            for (int j = 0; j < 8; j++) {
                mma16816(acc[j][0], acc[j][1], acc[j][2], acc[j][3],
                         ah0, ah1, ah2, ah3, bh[j][0], bh[j][1]);
            }
        }
    }

    // ---- epilogue: direct stores from accumulators ----
    const int r_lo = row0 + wm + (lane >> 2);
    const int c_base = col0 + wn + ((lane & 3) << 1);
#pragma unroll
    for (int j = 0; j < 8; j++) {
        int col = c_base + (j << 3);
#pragma unroll
        for (int half = 0; half < 2; half++) {
            int r = r_lo + (half << 3);
            float v0 = acc[j][half * 2 + 0] * scale;
            float v1 = acc[j][half * 2 + 1] * scale;
            if (mode == 1) {
                int b = r / seq;
                int s = r - b * seq;
                int h = col >> 6;
                int d = col & 63;
                float* op = out + (((size_t)(b * NH + h)) * seq + s) * 64 + d;
                op[0] = v0; op[1] = v1;
            } else {
                float* op = out + (size_t)r * ldc + col;
                op[0] = v0; op[1] = v1;
            }
        }
    }
}

// =========================================================================
// attn_kernel: banded attention with precomputed positional bias (per group)
// writes GATHERED output layout: [b*512+m, h*64+d]
// =========================================================================
#define AST 68

__global__ __launch_bounds__(256)
void attn_kernel(const float* __restrict__ gq, const float* __restrict__ gk,
                 const float* __restrict__ gv, const float* __restrict__ gP,
                 float* __restrict__ gout, int bh0)
{
    extern __shared__ float sm[];
    float (*sQ) [AST] = (float(*)[AST])(sm);
    float (*sKt)[AST] = (float(*)[AST])(sm + 64 * AST);
    float (*sV) [AST] = (float(*)[AST])(sm + 2 * 64 * AST);
    float (*sP) [AST] = (float(*)[AST])(sm + 3 * 64 * AST);

    const int tid = threadIdx.x;
    const int bhl = blockIdx.y;
    const int bh  = bh0 + bhl;
    const int m0  = blockIdx.x << 6;
    const int tx  = tid & 15;
    const int ty  = tid >> 4;
    const int tx4 = tx << 2;
    const int i0  = ty << 2;

    {
        int jl = tid >> 2;
        int db = (tid & 3) << 4;
        const float* qp = gq + ((((size_t)bh) * MQ + m0 + jl) << 6) + db;
#pragma unroll
        for (int u = 0; u < 4; u++)
            *(float4*)&sQ[jl][db + 4 * u] = *(const float4*)(qp + 4 * u);
    }

    float o[4][4];
#pragma unroll
    for (int a = 0; a < 4; a++)
#pragma unroll
        for (int b = 0; b < 4; b++) o[a][b] = 0.f;
    float mrow[4] = {-1e30f, -1e30f, -1e30f, -1e30f};
    float lrow[4] = {0.f, 0.f, 0.f, 0.f};
    const size_t Pbase = (((size_t)bhl) * MQ + m0) << 11;

    for (int c = 0; c <= 32; c++) {
        const int j0  = m0 + (c << 6);
        const int c64 = c << 6;
        __syncthreads();
        {
            int jl = tid >> 2;
            int db = (tid & 3) << 4;
            const size_t rb = (((size_t)bh) * NKV + j0 + jl) << 6;
            const float* kp = gk + rb + db;
            const float* vp = gv + rb + db;
#pragma unroll
            for (int u = 0; u < 4; u++) {
                float4 kk = *(const float4*)(kp + 4 * u);
                int dd = db + 4 * u;
                sKt[dd + 0][jl] = kk.x; sKt[dd + 1][jl] = kk.y;
                sKt[dd + 2][jl] = kk.z; sKt[dd + 3][jl] = kk.w;
                *(float4*)&sV[jl][dd] = *(const float4*)(vp + 4 * u);
            }
        }
        __syncthreads();

        float s[4][4];
#pragma unroll
        for (int a = 0; a < 4; a++)
#pragma unroll
            for (int b = 0; b < 4; b++) s[a][b] = 0.f;
#pragma unroll 4
        for (int d4 = 0; d4 < 64; d4 += 4) {
            float4 b0 = *(const float4*)&sKt[d4 + 0][tx4];
            float4 b1 = *(const float4*)&sKt[d4 + 1][tx4];
            float4 b2 = *(const float4*)&sKt[d4 + 2][tx4];
            float4 b3 = *(const float4*)&sKt[d4 + 3][tx4];
#pragma unroll
            for (int ui = 0; ui < 4; ui++) {
                float4 qa = *(const float4*)&sQ[i0 + ui][d4];
                s[ui][0] += qa.x * b0.x + qa.y * b1.x + qa.z * b2.x + qa.w * b3.x;
                s[ui][1] += qa.x * b0.y + qa.y * b1.y + qa.z * b2.y + qa.w * b3.y;
                s[ui][2] += qa.x * b0.z + qa.y * b1.z + qa.z * b2.z + qa.w * b3.z;
                s[ui][3] += qa.x * b0.w + qa.y * b1.w + qa.z * b2.w + qa.w * b3.w;
            }
        }

#pragma unroll
        for (int ui = 0; ui < 4; ui++) {
            const int i = i0 + ui;
            const float* Pr = gP + Pbase + (((size_t)i) << 11);
#pragma unroll
            for (int uj = 0; uj < 4; uj++) {
                int l = c64 + tx4 + uj - i;
                if ((unsigned)l < (unsigned)LW) s[ui][uj] += __ldg(Pr + l);
                else                            s[ui][uj] = -1e30f;
            }
        }

#pragma unroll
        for (int ui = 0; ui < 4; ui++) {
            float cm = fmaxf(fmaxf(s[ui][0], s[ui][1]), fmaxf(s[ui][2], s[ui][3]));
            cm = fmaxf(cm, __shfl_xor_sync(0xffffffffu, cm, 8));
            cm = fmaxf(cm, __shfl_xor_sync(0xffffffffu, cm, 4));
            cm = fmaxf(cm, __shfl_xor_sync(0xffffffffu, cm, 2));
            cm = fmaxf(cm, __shfl_xor_sync(0xffffffffu, cm, 1));
            float mnew = fmaxf(mrow[ui], cm);
            float corr = __expf(mrow[ui] - mnew);
            mrow[ui] = mnew;
            float ps = 0.f;
#pragma unroll
            for (int uj = 0; uj < 4; uj++) {
                float p = __expf(s[ui][uj] - mnew);
                s[ui][uj] = p;
                ps += p;
            }
            ps += __shfl_xor_sync(0xffffffffu, ps, 8);
            ps += __shfl_xor_sync(0xffffffffu, ps, 4);
            ps += __shfl_xor_sync(0xffffffffu, ps, 2);
            ps += __shfl_xor_sync(0xffffffffu, ps, 1);
            lrow[ui] = lrow[ui] * corr + ps;
            o[ui][0] *= corr; o[ui][1] *= corr; o[ui][2] *= corr; o[ui][3] *= corr;
        }

#pragma unroll
        for (int ui = 0; ui < 4; ui++)
#pragma unroll
            for (int uj = 0; uj < 4; uj++)
                sP[i0 + ui][tx4 + uj] = s[ui][uj];
        __syncthreads();

#pragma unroll 8
        for (int jj = 0; jj < 64; jj++) {
            float4 v4 = *(const float4*)&sV[jj][tx4];
            float p0 = sP[i0 + 0][jj];
            float p1 = sP[i0 + 1][jj];
            float p2 = sP[i0 + 2][jj];
            float p3 = sP[i0 + 3][jj];
            o[0][0] += p0 * v4.x; o[0][1] += p0 * v4.y; o[0][2] += p0 * v4.z; o[0][3] += p0 * v4.w;
            o[1][0] += p1 * v4.x; o[1][1] += p1 * v4.y; o[1][2] += p1 * v4.z; o[1][3] += p1 * v4.w;
            o[2][0] += p2 * v4.x; o[2][1] += p2 * v4.y; o[2][2] += p2 * v4.z; o[2][3] += p2 * v4.w;
            o[3][0] += p3 * v4.x; o[3][1] += p3 * v4.y; o[3][2] += p3 * v4.z; o[3][3] += p3 * v4.w;
        }
    }

    // epilogue (gathered layout: [b*512+m, h*64+d])
    const int bb = bh >> 4;
    const int h  = bh & 15;
#pragma unroll
    for (int ui = 0; ui < 4; ui++) {
        float inv = 1.f / lrow[ui];
        float4 r4 = make_float4(o[ui][0] * inv, o[ui][1] * inv, o[ui][2] * inv, o[ui][3] * inv);
        size_t row = (size_t)bb * MQ + m0 + i0 + ui;
        *(float4*)(gout + row * HID + (h << 6) + tx4) = r4;
    }
}

// =========================================================================
// host launcher
// =========================================================================
extern "C" void kernel_launch(void* const* d_in, const int* in_sizes, int n_in,
                              void* d_out, int out_size)
{
    const float* query  = (const float*)d_in[0];
    const float* key    = (const float*)d_in[1];
    const float* value  = (const float*)d_in[2];
    const float* key_pe = (const float*)d_in[3];
    const float* Wq     = (const float*)d_in[4];
    const float* Wk     = (const float*)d_in[5];
    const float* Wv     = (const float*)d_in[6];
    const float* Wo     = (const float*)d_in[7];
    float* out = (float*)d_out;

    float *pq, *pk, *pv, *pa, *pP;
    __nv_bfloat16 *wh, *wl, *peh, *pel;
    cudaGetSymbolAddress((void**)&pq, g_q);
    cudaGetSymbolAddress((void**)&pk, g_k);
    cudaGetSymbolAddress((void**)&pv, g_v);
    cudaGetSymbolAddress((void**)&pa, g_attn);
    cudaGetSymbolAddress((void**)&pP, g_P);
    cudaGetSymbolAddress((void**)&wh, g_wh);
    cudaGetSymbolAddress((void**)&wl, g_wl);
    cudaGetSymbolAddress((void**)&peh, g_peh);
    cudaGetSymbolAddress((void**)&pel, g_pel);

    const int nW4 = HID * HID / 4;
    const int wblk = (nW4 + 255) / 256;

    // ---- projections via mma.sync split-bf16 (weights pre-split) ----
    split_w<<<wblk, 256>>>(Wq, wh, wl, nW4);
    tc_gemm_mma<<<dim3(8, BB * MQ  / 64), 256>>>(query, wh, wl, pq, HID, HID, HID, MQ,  0.125f, 1);
    split_w<<<wblk, 256>>>(Wk, wh, wl, nW4);
    tc_gemm_mma<<<dim3(8, BB * NKV / 64), 256>>>(key,   wh, wl, pk, HID, HID, HID, NKV, 1.0f,   1);
    split_w<<<wblk, 256>>>(Wv, wh, wl, nW4);
    tc_gemm_mma<<<dim3(8, BB * NKV / 64), 256>>>(value, wh, wl, pv, HID, HID, HID, NKV, 1.0f,   1);

    // ---- pe^T pre-split, then grouped pos-bias GEMM + banded attention ----
    split_peT<<<(LW * HD + 255) / 256, 256>>>(key_pe, peh, pel);
    const int smem = 4 * 64 * AST * (int)sizeof(float);
    (void)cudaFuncSetAttribute(attn_kernel, cudaFuncAttributeMaxDynamicSharedMemorySize, smem);
    for (int g = 0; g < NGRP; g++) {
        const float* qg = pq + (size_t)g * GRP * MQ * HD;
        // P[8192, 2048] = qg[8192, 64] @ peT[2048, 64]^T
        tc_gemm_mma<<<dim3(LW / 128, GRP * MQ / 64), 256>>>(qg, peh, pel, pP, HD, HD, LW, MQ, 1.0f, 0);
        attn_kernel<<<dim3(8, GRP), 256, smem>>>(pq, pk, pv, pP, pa, g * GRP);
    }

    // ---- output projection (gathered input, row-major output) ----
    split_w<<<wblk, 256>>>(Wo, wh, wl, nW4);
    tc_gemm_mma<<<dim3(8, BB * MQ / 64), 256>>>(pa, wh, wl, out, HID, HID, HID, MQ, 1.0f, 0);
}

// round 14
// speedup vs baseline: 1.8005x; 1.2880x over previous
#include <cuda_runtime.h>
#include <cuda_bf16.h>
#include <cstdint>
#include <cstddef>

// Problem constants
#define BB     8
#define MQ     512
#define NKV    2560
#define NH     16
#define HD     64
#define HID    1024
#define LW     2048
#define BH     128   // BB*NH
#define GRP    16    // head-batches per group (for P buffer)
#define NGRP   8     // BH / GRP

// ---------------- scratch (device globals; no allocation) ----------------
__device__ float g_q   [(size_t)BH * MQ  * HD];      //  16.8 MB  [bh, m, d], pre-scaled 1/8 (fp32 for pe)
__device__ float g_attn[(size_t)BB * MQ  * HID];     //  16.8 MB  [b*512+m, h*64+d] (gathered)
__device__ float g_P   [(size_t)GRP * MQ * LW];      //  67.1 MB  [bh_local*512+m, l]
// K/V stored pre-split bf16 hi/lo
__device__ __nv_bfloat16 g_kh[(size_t)BH * NKV * HD];  // 41.9 MB
__device__ __nv_bfloat16 g_kl[(size_t)BH * NKV * HD];  // 41.9 MB
__device__ __nv_bfloat16 g_vh[(size_t)BH * NKV * HD];  // 41.9 MB
__device__ __nv_bfloat16 g_vl[(size_t)BH * NKV * HD];  // 41.9 MB
// pre-split bf16 B-operand buffers
__device__ __nv_bfloat16 g_wh [(size_t)HID * HID];   //   2 MB
__device__ __nv_bfloat16 g_wl [(size_t)HID * HID];   //   2 MB
__device__ __nv_bfloat16 g_peh[(size_t)LW * HD];     // 256 KB (pe^T hi: [l, d])
__device__ __nv_bfloat16 g_pel[(size_t)LW * HD];     // 256 KB (pe^T lo)

// ======================= helpers =============================
__device__ __forceinline__ uint32_t smem_u32(const void* p) {
    uint32_t a;
    asm("{ .reg .u64 t; cvta.to.shared.u64 t, %1; cvt.u32.u64 %0, t; }" : "=r"(a) : "l"(p));
    return a;
}
__device__ __forceinline__ void ldsm_x4(uint32_t& r0, uint32_t& r1, uint32_t& r2, uint32_t& r3,
                                        uint32_t addr) {
    asm volatile("ldmatrix.sync.aligned.m8n8.x4.shared.b16 {%0,%1,%2,%3}, [%4];"
                 : "=r"(r0), "=r"(r1), "=r"(r2), "=r"(r3) : "r"(addr));
}
__device__ __forceinline__ void ldsm_x4_t(uint32_t& r0, uint32_t& r1, uint32_t& r2, uint32_t& r3,
                                          uint32_t addr) {
    asm volatile("ldmatrix.sync.aligned.m8n8.x4.trans.shared.b16 {%0,%1,%2,%3}, [%4];"
                 : "=r"(r0), "=r"(r1), "=r"(r2), "=r"(r3) : "r"(addr));
}
__device__ __forceinline__ void mma16816(float& d0, float& d1, float& d2, float& d3,
                                         uint32_t a0, uint32_t a1, uint32_t a2, uint32_t a3,
                                         uint32_t b0, uint32_t b1) {
    asm volatile("mma.sync.aligned.m16n8k16.row.col.f32.bf16.bf16.f32 "
                 "{%0,%1,%2,%3}, {%4,%5,%6,%7}, {%8,%9}, {%0,%1,%2,%3};"
                 : "+f"(d0), "+f"(d1), "+f"(d2), "+f"(d3)
                 : "r"(a0), "r"(a1), "r"(a2), "r"(a3), "r"(b0), "r"(b1));
}
__device__ __forceinline__ void split2(float x, float y, uint32_t& hp, uint32_t& lp) {
    __nv_bfloat16 h0 = __float2bfloat16_rn(x), h1 = __float2bfloat16_rn(y);
    __nv_bfloat16 l0 = __float2bfloat16_rn(x - __bfloat162float(h0));
    __nv_bfloat16 l1 = __float2bfloat16_rn(y - __bfloat162float(h1));
    __nv_bfloat162 th(h0, h1), tl(l0, l1);
    hp = *(uint32_t*)&th; lp = *(uint32_t*)&tl;
}

// =========================================================================
// split_w: fp32 [n] -> bf16 hi/lo (elementwise, float4)
// =========================================================================
__global__ __launch_bounds__(256)
void split_w(const float* __restrict__ in, __nv_bfloat16* __restrict__ hi,
             __nv_bfloat16* __restrict__ lo, int n4)
{
    int i = blockIdx.x * 256 + threadIdx.x;
    if (i >= n4) return;
    float4 x = ((const float4*)in)[i];
    uint32_t h0, l0, h1, l1;
    split2(x.x, x.y, h0, l0);
    split2(x.z, x.w, h1, l1);
    ((uint2*)hi)[i] = make_uint2(h0, h1);
    ((uint2*)lo)[i] = make_uint2(l0, l1);
}

// =========================================================================
// split_peT: pe[d, l] (64 x 2048) -> peT hi/lo [l, d] (2048 x 64)
// =========================================================================
__global__ __launch_bounds__(256)
void split_peT(const float* __restrict__ pe, __nv_bfloat16* __restrict__ hi,
               __nv_bfloat16* __restrict__ lo)
{
    int idx = blockIdx.x * 256 + threadIdx.x;
    if (idx >= LW * HD) return;
    int d = idx & 63;
    int l = idx >> 6;
    float x = pe[(size_t)d * LW + l];
    __nv_bfloat16 h = __float2bfloat16_rn(x);
    __nv_bfloat16 ll = __float2bfloat16_rn(x - __bfloat162float(h));
    hi[idx] = h;
    lo[idx] = ll;
}

// =========================================================================
// mma.sync split-bf16 GEMM:  C[rows, N] = A[rows, K] @ B[N, K]^T
// mode 0: fp32 row-major (ldc). mode 1: fp32 head-scatter.
// mode 2: bf16 hi/lo head-scatter (outh/outl).
// =========================================================================
#define SA_H    0
#define SA_L    (64  * 80)
#define SB_H    (2 * 64 * 80)
#define SB_L    (SB_H + 128 * 80)
#define SMEMSZ  (SB_L + 128 * 80)

__global__ __launch_bounds__(256, 2)
void tc_gemm_mma(const float* __restrict__ A,
                 const __nv_bfloat16* __restrict__ Bh, const __nv_bfloat16* __restrict__ Bl,
                 float* __restrict__ out,
                 __nv_bfloat16* __restrict__ outh, __nv_bfloat16* __restrict__ outl,
                 int lda, int K, int ldc, int seq, float scale, int mode)
{
    __shared__ __align__(16) uint8_t smem[SMEMSZ];
    const uint32_t sb = smem_u32(smem);

    const int tid  = threadIdx.x;
    const int lane = tid & 31;
    const int wid  = tid >> 5;
    const int wm   = (wid & 3) << 4;
    const int wn   = (wid >> 2) << 6;
    const int row0 = blockIdx.y << 6;
    const int col0 = blockIdx.x << 7;

    float acc[8][4];
#pragma unroll
    for (int j = 0; j < 8; j++)
#pragma unroll
        for (int q = 0; q < 4; q++) acc[j][q] = 0.f;

    const int lrow = lane & 15;
    const int lcol = (lane >> 4) << 4;

    for (int ks = 0; ks < K; ks += 32) {
        __syncthreads();
#pragma unroll
        for (int u = 0; u < 2; u++) {
            int v = (u << 8) + tid;
            int r = v >> 3;
            int c4 = (v & 7) << 2;
            float4 x = *(const float4*)(A + (size_t)(row0 + r) * lda + ks + c4);
            uint32_t hp0, lp0, hp1, lp1;
            split2(x.x, x.y, hp0, lp0);
            split2(x.z, x.w, hp1, lp1);
            uint32_t off = r * 80 + (c4 << 1);
            *(uint2*)(smem + SA_H + off) = make_uint2(hp0, hp1);
            *(uint2*)(smem + SA_L + off) = make_uint2(lp0, lp1);
        }
#pragma unroll
        for (int u = 0; u < 2; u++) {
            int v = (u << 8) + tid;
            int r = v >> 2;
            int cb = (v & 3) << 3;
            uint32_t off = r * 80 + (cb << 1);
            *(uint4*)(smem + SB_H + off) = *(const uint4*)(Bh + (size_t)(col0 + r) * K + ks + cb);
            *(uint4*)(smem + SB_L + off) = *(const uint4*)(Bl + (size_t)(col0 + r) * K + ks + cb);
        }
        __syncthreads();

#pragma unroll
        for (int kk = 0; kk < 2; kk++) {
            const uint32_t kb = (kk << 5);
            uint32_t ah0, ah1, ah2, ah3, al0, al1, al2, al3;
            {
                uint32_t ar = sb + SA_H + (wm + lrow) * 80 + kb + lcol;
                ldsm_x4(ah0, ah1, ah2, ah3, ar);
                ldsm_x4(al0, al1, al2, al3, ar + (SA_L - SA_H));
            }
            uint32_t bh[8][2];
#pragma unroll
            for (int p = 0; p < 4; p++) {
                uint32_t br = sb + SB_H + (wn + (p << 4) + lrow) * 80 + kb + lcol;
                uint32_t r0, r1, r2, r3;
                ldsm_x4(r0, r1, r2, r3, br);
                bh[2*p][0] = r0; bh[2*p][1] = r2;
                bh[2*p+1][0] = r1; bh[2*p+1][1] = r3;
            }
#pragma unroll
            for (int j = 0; j < 8; j++) {
                mma16816(acc[j][0], acc[j][1], acc[j][2], acc[j][3],
                         ah0, ah1, ah2, ah3, bh[j][0], bh[j][1]);
                mma16816(acc[j][0], acc[j][1], acc[j][2], acc[j][3],
                         al0, al1, al2, al3, bh[j][0], bh[j][1]);
            }
#pragma unroll
            for (int p = 0; p < 4; p++) {
                uint32_t br = sb + SB_L + (wn + (p << 4) + lrow) * 80 + kb + lcol;
                uint32_t r0, r1, r2, r3;
                ldsm_x4(r0, r1, r2, r3, br);
                bh[2*p][0] = r0; bh[2*p][1] = r2;
                bh[2*p+1][0] = r1; bh[2*p+1][1] = r3;
            }
#pragma unroll
            for (int j = 0; j < 8; j++) {
                mma16816(acc[j][0], acc[j][1], acc[j][2], acc[j][3],
                         ah0, ah1, ah2, ah3, bh[j][0], bh[j][1]);
            }
        }
    }

    const int r_lo = row0 + wm + (lane >> 2);
    const int c_base = col0 + wn + ((lane & 3) << 1);
#pragma unroll
    for (int j = 0; j < 8; j++) {
        int col = c_base + (j << 3);
#pragma unroll
        for (int half = 0; half < 2; half++) {
            int r = r_lo + (half << 3);
            float v0 = acc[j][half * 2 + 0] * scale;
            float v1 = acc[j][half * 2 + 1] * scale;
            if (mode == 1) {
                int b = r / seq;
                int s = r - b * seq;
                int h = col >> 6;
                int d = col & 63;
                float* op = out + (((size_t)(b * NH + h)) * seq + s) * 64 + d;
                op[0] = v0; op[1] = v1;
            } else if (mode == 2) {
                int b = r / seq;
                int s = r - b * seq;
                int h = col >> 6;
                int d = col & 63;
                size_t off = (((size_t)(b * NH + h)) * seq + s) * 64 + d;
                uint32_t hp, lp;
                split2(v0, v1, hp, lp);
                *(uint32_t*)(outh + off) = hp;
                *(uint32_t*)(outl + off) = lp;
            } else {
                float* op = out + (size_t)r * ldc + col;
                op[0] = v0; op[1] = v1;
            }
        }
    }
}

// =========================================================================
// attn_mma: flash attention on mma.sync with precomputed pos-bias P.
// Block = (64-query m-tile, bh in group). 256 thr, warps 4(m) x 2(n).
// =========================================================================
#define AQ_H   0
#define AQ_L   9216
#define AK_H   18432
#define AK_L   27648
#define AVS_H  36864
#define AVS_L  46080
#define AP_H   55296
#define AP_L   64512
#define ARED   73728               // float [2][64] row-max partials
#define ARED2  74240               // float [2][64] row-sum partials
#define ASMEM  74752

__global__ __launch_bounds__(256)
void attn_mma(const float* __restrict__ gq,
              const __nv_bfloat16* __restrict__ gkh, const __nv_bfloat16* __restrict__ gkl,
              const __nv_bfloat16* __restrict__ gvh, const __nv_bfloat16* __restrict__ gvl,
              const float* __restrict__ gP, float* __restrict__ gout, int bh0)
{
    extern __shared__ __align__(16) char smc[];
    const uint32_t sb = smem_u32(smc);
    const int tid  = threadIdx.x;
    const int lane = tid & 31;
    const int wid  = tid >> 5;
    const int wm   = (wid & 3) << 4;
    const int wns  = (wid >> 2) << 5;
    const int nh   = wid >> 2;
    const int lrow = lane & 15;
    const int lcol = (lane >> 4) << 4;
    const int bhl  = blockIdx.y;
    const int bh   = bh0 + bhl;
    const int m0   = blockIdx.x << 6;

    // ---- load + split Q tile (64x64 fp32 -> bf16 hi/lo), once ----
    {
        const float* qp = gq + (((size_t)bh * MQ + m0) << 6);
#pragma unroll
        for (int u = 0; u < 4; u++) {
            int v = (u << 8) + tid;
            int r = v >> 4;
            int c4 = (v & 15) << 2;
            float4 x = *(const float4*)(qp + (r << 6) + c4);
            uint32_t hp0, lp0, hp1, lp1;
            split2(x.x, x.y, hp0, lp0);
            split2(x.z, x.w, hp1, lp1);
            uint32_t off = r * 144 + (c4 << 1);
            *(uint2*)(smc + AQ_H + off) = make_uint2(hp0, hp1);
            *(uint2*)(smc + AQ_L + off) = make_uint2(lp0, lp1);
        }
    }

    float o4[4][4];
#pragma unroll
    for (int t = 0; t < 4; t++)
#pragma unroll
        for (int q = 0; q < 4; q++) o4[t][q] = 0.f;
    float mr1 = -1e30f, mr2 = -1e30f, lr1 = 0.f, lr2 = 0.f;

    const int r1 = wm + (lane >> 2);
    const int r2 = r1 + 8;
    const size_t Pbase = (((size_t)bhl) * MQ + m0) << 11;
    const float* P1 = gP + Pbase + ((size_t)r1 << 11);
    const float* P2 = gP + Pbase + ((size_t)r2 << 11);
    float* redm = (float*)(smc + ARED);
    float* reds = (float*)(smc + ARED2);

    for (int c = 0; c <= 32; c++) {
        const int c64 = c << 6;
        const int j0  = m0 + c64;
        __syncthreads();
        // ---- stage K/V (bf16 hi/lo, pure copies) ----
        {
            const size_t kvb = ((size_t)bh * NKV + j0) << 6;
#pragma unroll
            for (int u = 0; u < 8; u++) {
                int v = (u << 8) + tid;
                int rem = v & 511;
                int row = rem >> 3;
                int sg = (rem & 7) << 3;
                const __nv_bfloat16* sp = (u < 2) ? gkh : (u < 4) ? gkl : (u < 6) ? gvh : gvl;
                const uint32_t db = (u < 2) ? AK_H : (u < 4) ? AK_L : (u < 6) ? AVS_H : AVS_L;
                *(uint4*)(smc + db + row * 144 + (sg << 1)) =
                    *(const uint4*)(sp + kvb + ((size_t)row << 6) + sg);
            }
        }
        __syncthreads();

        // ---- QK: S[64x64], warp tile 16 x 32 (4 n-tiles), 3 passes ----
        float s4[4][4];
#pragma unroll
        for (int t = 0; t < 4; t++)
#pragma unroll
            for (int q = 0; q < 4; q++) s4[t][q] = 0.f;
#pragma unroll
        for (int kk = 0; kk < 4; kk++) {
            const uint32_t kb = kk << 5;
            uint32_t qh[4], ql[4];
            {
                uint32_t ar = sb + AQ_H + (wm + lrow) * 144 + kb + lcol;
                ldsm_x4(qh[0], qh[1], qh[2], qh[3], ar);
                ldsm_x4(ql[0], ql[1], ql[2], ql[3], ar + (AQ_L - AQ_H));
            }
            uint32_t bkh[4][2], bkl[4][2];
#pragma unroll
            for (int p = 0; p < 2; p++) {
                uint32_t br = sb + AK_H + (wns + (p << 4) + lrow) * 144 + kb + lcol;
                uint32_t t0, t1, t2, t3;
                ldsm_x4(t0, t1, t2, t3, br);
                bkh[2*p][0] = t0; bkh[2*p][1] = t2;
                bkh[2*p+1][0] = t1; bkh[2*p+1][1] = t3;
                ldsm_x4(t0, t1, t2, t3, br + (AK_L - AK_H));
                bkl[2*p][0] = t0; bkl[2*p][1] = t2;
                bkl[2*p+1][0] = t1; bkl[2*p+1][1] = t3;
            }
#pragma unroll
            for (int t = 0; t < 4; t++) {
                mma16816(s4[t][0], s4[t][1], s4[t][2], s4[t][3],
                         qh[0], qh[1], qh[2], qh[3], bkh[t][0], bkh[t][1]);
                mma16816(s4[t][0], s4[t][1], s4[t][2], s4[t][3],
                         ql[0], ql[1], ql[2], ql[3], bkh[t][0], bkh[t][1]);
                mma16816(s4[t][0], s4[t][1], s4[t][2], s4[t][3],
                         qh[0], qh[1], qh[2], qh[3], bkl[t][0], bkl[t][1]);
            }
        }

        // ---- pos-bias + band mask (l = c64 + jj - i, valid iff 0<=l<2048) ----
#pragma unroll
        for (int t = 0; t < 4; t++) {
            const int ct = wns + (t << 3) + ((lane & 3) << 1);
            int l1 = c64 + ct - r1;
            int l2 = c64 + ct - r2;
            if ((unsigned)l1 < (unsigned)LW) s4[t][0] += __ldg(P1 + l1); else s4[t][0] = -1e30f;
            if ((unsigned)(l1+1) < (unsigned)LW) s4[t][1] += __ldg(P1 + l1 + 1); else s4[t][1] = -1e30f;
            if ((unsigned)l2 < (unsigned)LW) s4[t][2] += __ldg(P2 + l2); else s4[t][2] = -1e30f;
            if ((unsigned)(l2+1) < (unsigned)LW) s4[t][3] += __ldg(P2 + l2 + 1); else s4[t][3] = -1e30f;
        }

        // ---- online softmax: quad-shfl partials + cross-warp smem combine ----
        float pm1 = -1e30f, pm2 = -1e30f;
#pragma unroll
        for (int t = 0; t < 4; t++) {
            pm1 = fmaxf(pm1, fmaxf(s4[t][0], s4[t][1]));
            pm2 = fmaxf(pm2, fmaxf(s4[t][2], s4[t][3]));
        }
        pm1 = fmaxf(pm1, __shfl_xor_sync(0xffffffffu, pm1, 1));
        pm1 = fmaxf(pm1, __shfl_xor_sync(0xffffffffu, pm1, 2));
        pm2 = fmaxf(pm2, __shfl_xor_sync(0xffffffffu, pm2, 1));
        pm2 = fmaxf(pm2, __shfl_xor_sync(0xffffffffu, pm2, 2));
        if ((lane & 3) == 0) { redm[nh * 64 + r1] = pm1; redm[nh * 64 + r2] = pm2; }
        __syncthreads();
        const float cm1 = fmaxf(redm[r1], redm[64 + r1]);
        const float cm2 = fmaxf(redm[r2], redm[64 + r2]);
        const float mn1 = fmaxf(mr1, cm1), mn2 = fmaxf(mr2, cm2);
        const float corr1 = __expf(mr1 - mn1), corr2 = __expf(mr2 - mn2);
        mr1 = mn1; mr2 = mn2;
        float ps1 = 0.f, ps2 = 0.f;
#pragma unroll
        for (int t = 0; t < 4; t++) {
            const int ct = wns + (t << 3) + ((lane & 3) << 1);
            float e0 = __expf(s4[t][0] - mn1);
            float e1 = __expf(s4[t][1] - mn1);
            float e2 = __expf(s4[t][2] - mn2);
            float e3 = __expf(s4[t][3] - mn2);
            ps1 += e0 + e1;
            ps2 += e2 + e3;
            uint32_t hp, lp;
            split2(e0, e1, hp, lp);
            *(uint32_t*)(smc + AP_H + r1 * 144 + (ct << 1)) = hp;
            *(uint32_t*)(smc + AP_L + r1 * 144 + (ct << 1)) = lp;
            split2(e2, e3, hp, lp);
            *(uint32_t*)(smc + AP_H + r2 * 144 + (ct << 1)) = hp;
            *(uint32_t*)(smc + AP_L + r2 * 144 + (ct << 1)) = lp;
        }
        ps1 += __shfl_xor_sync(0xffffffffu, ps1, 1);
        ps1 += __shfl_xor_sync(0xffffffffu, ps1, 2);
        ps2 += __shfl_xor_sync(0xffffffffu, ps2, 1);
        ps2 += __shfl_xor_sync(0xffffffffu, ps2, 2);
        if ((lane & 3) == 0) { reds[nh * 64 + r1] = ps1; reds[nh * 64 + r2] = ps2; }
        __syncthreads();
        lr1 = lr1 * corr1 + reds[r1] + reds[64 + r1];
        lr2 = lr2 * corr2 + reds[r2] + reds[64 + r2];
#pragma unroll
        for (int t = 0; t < 4; t++) {
            o4[t][0] *= corr1; o4[t][1] *= corr1;
            o4[t][2] *= corr2; o4[t][3] *= corr2;
        }

        // ---- AV: O += P @ V, V^T via ldsm.trans, 3 passes ----
#pragma unroll
        for (int kk = 0; kk < 4; kk++) {
            const uint32_t kb = kk << 5;
            uint32_t ph[4], pl[4];
            {
                uint32_t ar = sb + AP_H + (wm + lrow) * 144 + kb + lcol;
                ldsm_x4(ph[0], ph[1], ph[2], ph[3], ar);
                ldsm_x4(pl[0], pl[1], pl[2], pl[3], ar + (AP_L - AP_H));
            }
            uint32_t bvh[4][2], bvl[4][2];
#pragma unroll
            for (int p = 0; p < 2; p++) {
                uint32_t br = sb + AVS_H + ((kk << 4) + lrow) * 144 + ((wns + (p << 4)) << 1) + lcol;
                uint32_t t0, t1, t2, t3;
                ldsm_x4_t(t0, t1, t2, t3, br);
                bvh[2*p][0] = t0; bvh[2*p][1] = t1;
                bvh[2*p+1][0] = t2; bvh[2*p+1][1] = t3;
                ldsm_x4_t(t0, t1, t2, t3, br + (AVS_L - AVS_H));
                bvl[2*p][0] = t0; bvl[2*p][1] = t1;
                bvl[2*p+1][0] = t2; bvl[2*p+1][1] = t3;
            }
#pragma unroll
            for (int t = 0; t < 4; t++) {
                mma16816(o4[t][0], o4[t][1], o4[t][2], o4[t][3],
                         ph[0], ph[1], ph[2], ph[3], bvh[t][0], bvh[t][1]);
                mma16816(o4[t][0], o4[t][1], o4[t][2], o4[t][3],
                         pl[0], pl[1], pl[2], pl[3], bvh[t][0], bvh[t][1]);
                mma16816(o4[t][0], o4[t][1], o4[t][2], o4[t][3],
                         ph[0], ph[1], ph[2], ph[3], bvl[t][0], bvl[t][1]);
            }
        }
    }

    // ---- epilogue: normalize, write gathered fp32 ----
    const float inv1 = 1.f / lr1;
    const float inv2 = 1.f / lr2;
    const int bb = bh >> 4;
    const int hh = bh & 15;
    const size_t grow1 = (size_t)bb * MQ + m0 + r1;
    const size_t grow2 = (size_t)bb * MQ + m0 + r2;
#pragma unroll
    for (int t = 0; t < 4; t++) {
        const int dt = wns + (t << 3) + ((lane & 3) << 1);
        float2 a = make_float2(o4[t][0] * inv1, o4[t][1] * inv1);
        float2 b = make_float2(o4[t][2] * inv2, o4[t][3] * inv2);
        *(float2*)(gout + grow1 * HID + (hh << 6) + dt) = a;
        *(float2*)(gout + grow2 * HID + (hh << 6) + dt) = b;
    }
}

// =========================================================================
// host launcher
// =========================================================================
extern "C" void kernel_launch(void* const* d_in, const int* in_sizes, int n_in,
                              void* d_out, int out_size)
{
    const float* query  = (const float*)d_in[0];
    const float* key    = (const float*)d_in[1];
    const float* value  = (const float*)d_in[2];
    const float* key_pe = (const float*)d_in[3];
    const float* Wq     = (const float*)d_in[4];
    const float* Wk     = (const float*)d_in[5];
    const float* Wv     = (const float*)d_in[6];
    const float* Wo     = (const float*)d_in[7];
    float* out = (float*)d_out;

    float *pq, *pa, *pP;
    __nv_bfloat16 *kh, *kl, *vh, *vl, *wh, *wl, *peh, *pel;
    cudaGetSymbolAddress((void**)&pq, g_q);
    cudaGetSymbolAddress((void**)&pa, g_attn);
    cudaGetSymbolAddress((void**)&pP, g_P);
    cudaGetSymbolAddress((void**)&kh, g_kh);
    cudaGetSymbolAddress((void**)&kl, g_kl);
    cudaGetSymbolAddress((void**)&vh, g_vh);
    cudaGetSymbolAddress((void**)&vl, g_vl);
    cudaGetSymbolAddress((void**)&wh, g_wh);
    cudaGetSymbolAddress((void**)&wl, g_wl);
    cudaGetSymbolAddress((void**)&peh, g_peh);
    cudaGetSymbolAddress((void**)&pel, g_pel);

    const int nW4 = HID * HID / 4;
    const int wblk = (nW4 + 255) / 256;

    // ---- projections (Q fp32 head-scatter; K/V split-bf16 head-scatter) ----
    split_w<<<wblk, 256>>>(Wq, wh, wl, nW4);
    tc_gemm_mma<<<dim3(8, BB * MQ  / 64), 256>>>(query, wh, wl, pq, nullptr, nullptr,
                                                 HID, HID, HID, MQ,  0.125f, 1);
    split_w<<<wblk, 256>>>(Wk, wh, wl, nW4);
    tc_gemm_mma<<<dim3(8, BB * NKV / 64), 256>>>(key,   wh, wl, nullptr, kh, kl,
                                                 HID, HID, HID, NKV, 1.0f,   2);
    split_w<<<wblk, 256>>>(Wv, wh, wl, nW4);
    tc_gemm_mma<<<dim3(8, BB * NKV / 64), 256>>>(value, wh, wl, nullptr, vh, vl,
                                                 HID, HID, HID, NKV, 1.0f,   2);

    // ---- pe^T pre-split, then grouped pos-bias GEMM + mma attention ----
    split_peT<<<(LW * HD + 255) / 256, 256>>>(key_pe, peh, pel);
    (void)cudaFuncSetAttribute(attn_mma, cudaFuncAttributeMaxDynamicSharedMemorySize, ASMEM);
    for (int g = 0; g < NGRP; g++) {
        const float* qg = pq + (size_t)g * GRP * MQ * HD;
        tc_gemm_mma<<<dim3(LW / 128, GRP * MQ / 64), 256>>>(qg, peh, pel, pP, nullptr, nullptr,
                                                            HD, HD, LW, MQ, 1.0f, 0);
        attn_mma<<<dim3(8, GRP), 256, ASMEM>>>(pq, kh, kl, vh, vl, pP, pa, g * GRP);
    }

    // ---- output projection ----
    split_w<<<wblk, 256>>>(Wo, wh, wl, nW4);
    tc_gemm_mma<<<dim3(8, BB * MQ / 64), 256>>>(pa, wh, wl, out, nullptr, nullptr,
                                                HID, HID, HID, MQ, 1.0f, 0);
}

// round 15
// speedup vs baseline: 1.8007x; 1.0001x over previous
#include <cuda_runtime.h>
#include <cuda_bf16.h>
#include <cstdint>
#include <cstddef>

// Problem constants
#define BB     8
#define MQ     512
#define NKV    2560
#define NH     16
#define HD     64
#define HID    1024
#define LW     2048
#define BH     128   // BB*NH
#define GRP    16    // head-batches per group (for P buffer)
#define NGRP   8     // BH / GRP

// ---------------- scratch (device globals; no allocation) ----------------
__device__ float g_q   [(size_t)BH * MQ  * HD];      //  16.8 MB  [bh, m, d], pre-scaled 1/8 (fp32 for pe)
__device__ float g_attn[(size_t)BB * MQ  * HID];     //  16.8 MB  [b*512+m, h*64+d] (gathered)
__device__ float g_P   [(size_t)GRP * MQ * LW];      //  67.1 MB  [bh_local*512+m, l]
// K/V stored pre-split bf16 hi/lo
__device__ __nv_bfloat16 g_kh[(size_t)BH * NKV * HD];  // 41.9 MB
__device__ __nv_bfloat16 g_kl[(size_t)BH * NKV * HD];  // 41.9 MB
__device__ __nv_bfloat16 g_vh[(size_t)BH * NKV * HD];  // 41.9 MB
__device__ __nv_bfloat16 g_vl[(size_t)BH * NKV * HD];  // 41.9 MB
// pre-split bf16 B-operand buffers
__device__ __nv_bfloat16 g_wh [(size_t)HID * HID];   //   2 MB
__device__ __nv_bfloat16 g_wl [(size_t)HID * HID];   //   2 MB
__device__ __nv_bfloat16 g_peh[(size_t)LW * HD];     // 256 KB (pe^T hi: [l, d])
__device__ __nv_bfloat16 g_pel[(size_t)LW * HD];     // 256 KB (pe^T lo)

// ======================= helpers =============================
__device__ __forceinline__ uint32_t smem_u32(const void* p) {
    uint32_t a;
    asm("{ .reg .u64 t; cvta.to.shared.u64 t, %1; cvt.u32.u64 %0, t; }" : "=r"(a) : "l"(p));
    return a;
}
__device__ __forceinline__ void ldsm_x4(uint32_t& r0, uint32_t& r1, uint32_t& r2, uint32_t& r3,
                                        uint32_t addr) {
    asm volatile("ldmatrix.sync.aligned.m8n8.x4.shared.b16 {%0,%1,%2,%3}, [%4];"
                 : "=r"(r0), "=r"(r1), "=r"(r2), "=r"(r3) : "r"(addr));
}
__device__ __forceinline__ void ldsm_x4_t(uint32_t& r0, uint32_t& r1, uint32_t& r2, uint32_t& r3,
                                          uint32_t addr) {
    asm volatile("ldmatrix.sync.aligned.m8n8.x4.trans.shared.b16 {%0,%1,%2,%3}, [%4];"
                 : "=r"(r0), "=r"(r1), "=r"(r2), "=r"(r3) : "r"(addr));
}
__device__ __forceinline__ void mma16816(float& d0, float& d1, float& d2, float& d3,
                                         uint32_t a0, uint32_t a1, uint32_t a2, uint32_t a3,
                                         uint32_t b0, uint32_t b1) {
    asm volatile("mma.sync.aligned.m16n8k16.row.col.f32.bf16.bf16.f32 "
                 "{%0,%1,%2,%3}, {%4,%5,%6,%7}, {%8,%9}, {%0,%1,%2,%3};"
                 : "+f"(d0), "+f"(d1), "+f"(d2), "+f"(d3)
                 : "r"(a0), "r"(a1), "r"(a2), "r"(a3), "r"(b0), "r"(b1));
}
__device__ __forceinline__ void split2(float x, float y, uint32_t& hp, uint32_t& lp) {
    __nv_bfloat16 h0 = __float2bfloat16_rn(x), h1 = __float2bfloat16_rn(y);
    __nv_bfloat16 l0 = __float2bfloat16_rn(x - __bfloat162float(h0));
    __nv_bfloat16 l1 = __float2bfloat16_rn(y - __bfloat162float(h1));
    __nv_bfloat162 th(h0, h1), tl(l0, l1);
    hp = *(uint32_t*)&th; lp = *(uint32_t*)&tl;
}

// =========================================================================
// split_w: fp32 [n] -> bf16 hi/lo (elementwise, float4)
// =========================================================================
__global__ __launch_bounds__(256)
void split_w(const float* __restrict__ in, __nv_bfloat16* __restrict__ hi,
             __nv_bfloat16* __restrict__ lo, int n4)
{
    int i = blockIdx.x * 256 + threadIdx.x;
    if (i >= n4) return;
    float4 x = ((const float4*)in)[i];
    uint32_t h0, l0, h1, l1;
    split2(x.x, x.y, h0, l0);
    split2(x.z, x.w, h1, l1);
    ((uint2*)hi)[i] = make_uint2(h0, h1);
    ((uint2*)lo)[i] = make_uint2(l0, l1);
}

// =========================================================================
// split_peT: pe[d, l] (64 x 2048) -> peT hi/lo [l, d] (2048 x 64)
// =========================================================================
__global__ __launch_bounds__(256)
void split_peT(const float* __restrict__ pe, __nv_bfloat16* __restrict__ hi,
               __nv_bfloat16* __restrict__ lo)
{
    int idx = blockIdx.x * 256 + threadIdx.x;
    if (idx >= LW * HD) return;
    int d = idx & 63;
    int l = idx >> 6;
    float x = pe[(size_t)d * LW + l];
    __nv_bfloat16 h = __float2bfloat16_rn(x);
    __nv_bfloat16 ll = __float2bfloat16_rn(x - __bfloat162float(h));
    hi[idx] = h;
    lo[idx] = ll;
}

// =========================================================================
// mma.sync split-bf16 GEMM:  C[rows, N] = A[rows, K] @ B[N, K]^T
// mode 0: fp32 row-major (ldc). mode 1: fp32 head-scatter.
// mode 2: bf16 hi/lo head-scatter (outh/outl).
// =========================================================================
#define SA_H    0
#define SA_L    (64  * 80)
#define SB_H    (2 * 64 * 80)
#define SB_L    (SB_H + 128 * 80)
#define SMEMSZ  (SB_L + 128 * 80)

__global__ __launch_bounds__(256, 2)
void tc_gemm_mma(const float* __restrict__ A,
                 const __nv_bfloat16* __restrict__ Bh, const __nv_bfloat16* __restrict__ Bl,
                 float* __restrict__ out,
                 __nv_bfloat16* __restrict__ outh, __nv_bfloat16* __restrict__ outl,
                 int lda, int K, int ldc, int seq, float scale, int mode)
{
    __shared__ __align__(16) uint8_t smem[SMEMSZ];
    const uint32_t sb = smem_u32(smem);

    const int tid  = threadIdx.x;
    const int lane = tid & 31;
    const int wid  = tid >> 5;
    const int wm   = (wid & 3) << 4;
    const int wn   = (wid >> 2) << 6;
    const int row0 = blockIdx.y << 6;
    const int col0 = blockIdx.x << 7;

    float acc[8][4];
#pragma unroll
    for (int j = 0; j < 8; j++)
#pragma unroll
        for (int q = 0; q < 4; q++) acc[j][q] = 0.f;

    const int lrow = lane & 15;
    const int lcol = (lane >> 4) << 4;

    for (int ks = 0; ks < K; ks += 32) {
        __syncthreads();
#pragma unroll
        for (int u = 0; u < 2; u++) {
            int v = (u << 8) + tid;
            int r = v >> 3;
            int c4 = (v & 7) << 2;
            float4 x = *(const float4*)(A + (size_t)(row0 + r) * lda + ks + c4);
            uint32_t hp0, lp0, hp1, lp1;
            split2(x.x, x.y, hp0, lp0);
            split2(x.z, x.w, hp1, lp1);
            uint32_t off = r * 80 + (c4 << 1);
            *(uint2*)(smem + SA_H + off) = make_uint2(hp0, hp1);
            *(uint2*)(smem + SA_L + off) = make_uint2(lp0, lp1);
        }
#pragma unroll
        for (int u = 0; u < 2; u++) {
            int v = (u << 8) + tid;
            int r = v >> 2;
            int cb = (v & 3) << 3;
            uint32_t off = r * 80 + (cb << 1);
            *(uint4*)(smem + SB_H + off) = *(const uint4*)(Bh + (size_t)(col0 + r) * K + ks + cb);
            *(uint4*)(smem + SB_L + off) = *(const uint4*)(Bl + (size_t)(col0 + r) * K + ks + cb);
        }
        __syncthreads();

#pragma unroll
        for (int kk = 0; kk < 2; kk++) {
            const uint32_t kb = (kk << 5);
            uint32_t ah0, ah1, ah2, ah3, al0, al1, al2, al3;
            {
                uint32_t ar = sb + SA_H + (wm + lrow) * 80 + kb + lcol;
                ldsm_x4(ah0, ah1, ah2, ah3, ar);
                ldsm_x4(al0, al1, al2, al3, ar + (SA_L - SA_H));
            }
            uint32_t bh[8][2];
#pragma unroll
            for (int p = 0; p < 4; p++) {
                uint32_t br = sb + SB_H + (wn + (p << 4) + lrow) * 80 + kb + lcol;
                uint32_t r0, r1, r2, r3;
                ldsm_x4(r0, r1, r2, r3, br);
                bh[2*p][0] = r0; bh[2*p][1] = r2;
                bh[2*p+1][0] = r1; bh[2*p+1][1] = r3;
            }
#pragma unroll
            for (int j = 0; j < 8; j++) {
                mma16816(acc[j][0], acc[j][1], acc[j][2], acc[j][3],
                         ah0, ah1, ah2, ah3, bh[j][0], bh[j][1]);
                mma16816(acc[j][0], acc[j][1], acc[j][2], acc[j][3],
                         al0, al1, al2, al3, bh[j][0], bh[j][1]);
            }
#pragma unroll
            for (int p = 0; p < 4; p++) {
                uint32_t br = sb + SB_L + (wn + (p << 4) + lrow) * 80 + kb + lcol;
                uint32_t r0, r1, r2, r3;
                ldsm_x4(r0, r1, r2, r3, br);
                bh[2*p][0] = r0; bh[2*p][1] = r2;
                bh[2*p+1][0] = r1; bh[2*p+1][1] = r3;
            }
#pragma unroll
            for (int j = 0; j < 8; j++) {
                mma16816(acc[j][0], acc[j][1], acc[j][2], acc[j][3],
                         ah0, ah1, ah2, ah3, bh[j][0], bh[j][1]);
            }
        }
    }

    const int r_lo = row0 + wm + (lane >> 2);
    const int c_base = col0 + wn + ((lane & 3) << 1);
#pragma unroll
    for (int j = 0; j < 8; j++) {
        int col = c_base + (j << 3);
#pragma unroll
        for (int half = 0; half < 2; half++) {
            int r = r_lo + (half << 3);
            float v0 = acc[j][half * 2 + 0] * scale;
            float v1 = acc[j][half * 2 + 1] * scale;
            if (mode == 1) {
                int b = r / seq;
                int s = r - b * seq;
                int h = col >> 6;
                int d = col & 63;
                float* op = out + (((size_t)(b * NH + h)) * seq + s) * 64 + d;
                op[0] = v0; op[1] = v1;
            } else if (mode == 2) {
                int b = r / seq;
                int s = r - b * seq;
                int h = col >> 6;
                int d = col & 63;
                size_t off = (((size_t)(b * NH + h)) * seq + s) * 64 + d;
                uint32_t hp, lp;
                split2(v0, v1, hp, lp);
                *(uint32_t*)(outh + off) = hp;
                *(uint32_t*)(outl + off) = lp;
            } else {
                float* op = out + (size_t)r * ldc + col;
                op[0] = v0; op[1] = v1;
            }
        }
    }
}

// =========================================================================
// attn_mma: flash attention on mma.sync with precomputed pos-bias P.
// Block = (64-query m-tile, bh in group). 256 thr, warps 4(m) x 2(n).
// =========================================================================
#define AQ_H   0
#define AQ_L   9216
#define AK_H   18432
#define AK_L   27648
#define AVS_H  36864
#define AVS_L  46080
#define AP_H   55296
#define AP_L   64512
#define ARED   73728               // float [2][64] row-max partials
#define ARED2  74240               // float [2][64] row-sum partials
#define ASMEM  74752

__global__ __launch_bounds__(256)
void attn_mma(const float* __restrict__ gq,
              const __nv_bfloat16* __restrict__ gkh, const __nv_bfloat16* __restrict__ gkl,
              const __nv_bfloat16* __restrict__ gvh, const __nv_bfloat16* __restrict__ gvl,
              const float* __restrict__ gP, float* __restrict__ gout, int bh0)
{
    extern __shared__ __align__(16) char smc[];
    const uint32_t sb = smem_u32(smc);
    const int tid  = threadIdx.x;
    const int lane = tid & 31;
    const int wid  = tid >> 5;
    const int wm   = (wid & 3) << 4;
    const int wns  = (wid >> 2) << 5;
    const int nh   = wid >> 2;
    const int lrow = lane & 15;
    const int lcol = (lane >> 4) << 4;
    const int bhl  = blockIdx.y;
    const int bh   = bh0 + bhl;
    const int m0   = blockIdx.x << 6;

    // ---- load + split Q tile (64x64 fp32 -> bf16 hi/lo), once ----
    {
        const float* qp = gq + (((size_t)bh * MQ + m0) << 6);
#pragma unroll
        for (int u = 0; u < 4; u++) {
            int v = (u << 8) + tid;
            int r = v >> 4;
            int c4 = (v & 15) << 2;
            float4 x = *(const float4*)(qp + (r << 6) + c4);
            uint32_t hp0, lp0, hp1, lp1;
            split2(x.x, x.y, hp0, lp0);
            split2(x.z, x.w, hp1, lp1);
            uint32_t off = r * 144 + (c4 << 1);
            *(uint2*)(smc + AQ_H + off) = make_uint2(hp0, hp1);
            *(uint2*)(smc + AQ_L + off) = make_uint2(lp0, lp1);
        }
    }

    float o4[4][4];
#pragma unroll
    for (int t = 0; t < 4; t++)
#pragma unroll
        for (int q = 0; q < 4; q++) o4[t][q] = 0.f;
    float mr1 = -1e30f, mr2 = -1e30f, lr1 = 0.f, lr2 = 0.f;

    const int r1 = wm + (lane >> 2);
    const int r2 = r1 + 8;
    const size_t Pbase = (((size_t)bhl) * MQ + m0) << 11;
    const float* P1 = gP + Pbase + ((size_t)r1 << 11);
    const float* P2 = gP + Pbase + ((size_t)r2 << 11);
    float* redm = (float*)(smc + ARED);
    float* reds = (float*)(smc + ARED2);

    for (int c = 0; c <= 32; c++) {
        const int c64 = c << 6;
        const int j0  = m0 + c64;
        __syncthreads();
        // ---- stage K/V (bf16 hi/lo, pure copies) ----
        {
            const size_t kvb = ((size_t)bh * NKV + j0) << 6;
#pragma unroll
            for (int u = 0; u < 8; u++) {
                int v = (u << 8) + tid;
                int rem = v & 511;
                int row = rem >> 3;
                int sg = (rem & 7) << 3;
                const __nv_bfloat16* sp = (u < 2) ? gkh : (u < 4) ? gkl : (u < 6) ? gvh : gvl;
                const uint32_t db = (u < 2) ? AK_H : (u < 4) ? AK_L : (u < 6) ? AVS_H : AVS_L;
                *(uint4*)(smc + db + row * 144 + (sg << 1)) =
                    *(const uint4*)(sp + kvb + ((size_t)row << 6) + sg);
            }
        }
        __syncthreads();

        // ---- QK: S[64x64], warp tile 16 x 32 (4 n-tiles), 3 passes ----
        float s4[4][4];
#pragma unroll
        for (int t = 0; t < 4; t++)
#pragma unroll
            for (int q = 0; q < 4; q++) s4[t][q] = 0.f;
#pragma unroll
        for (int kk = 0; kk < 4; kk++) {
            const uint32_t kb = kk << 5;
            uint32_t qh[4], ql[4];
            {
                uint32_t ar = sb + AQ_H + (wm + lrow) * 144 + kb + lcol;
                ldsm_x4(qh[0], qh[1], qh[2], qh[3], ar);
                ldsm_x4(ql[0], ql[1], ql[2], ql[3], ar + (AQ_L - AQ_H));
            }
            uint32_t bkh[4][2], bkl[4][2];
#pragma unroll
            for (int p = 0; p < 2; p++) {
                uint32_t br = sb + AK_H + (wns + (p << 4) + lrow) * 144 + kb + lcol;
                uint32_t t0, t1, t2, t3;
                ldsm_x4(t0, t1, t2, t3, br);
                bkh[2*p][0] = t0; bkh[2*p][1] = t2;
                bkh[2*p+1][0] = t1; bkh[2*p+1][1] = t3;
                ldsm_x4(t0, t1, t2, t3, br + (AK_L - AK_H));
                bkl[2*p][0] = t0; bkl[2*p][1] = t2;
                bkl[2*p+1][0] = t1; bkl[2*p+1][1] = t3;
            }
#pragma unroll
            for (int t = 0; t < 4; t++) {
                mma16816(s4[t][0], s4[t][1], s4[t][2], s4[t][3],
                         qh[0], qh[1], qh[2], qh[3], bkh[t][0], bkh[t][1]);
                mma16816(s4[t][0], s4[t][1], s4[t][2], s4[t][3],
                         ql[0], ql[1], ql[2], ql[3], bkh[t][0], bkh[t][1]);
                mma16816(s4[t][0], s4[t][1], s4[t][2], s4[t][3],
                         qh[0], qh[1], qh[2], qh[3], bkl[t][0], bkl[t][1]);
            }
        }

        // ---- pos-bias + band mask (l = c64 + jj - i, valid iff 0<=l<2048) ----
#pragma unroll
        for (int t = 0; t < 4; t++) {
            const int ct = wns + (t << 3) + ((lane & 3) << 1);
            int l1 = c64 + ct - r1;
            int l2 = c64 + ct - r2;
            if ((unsigned)l1 < (unsigned)LW) s4[t][0] += __ldg(P1 + l1); else s4[t][0] = -1e30f;
            if ((unsigned)(l1+1) < (unsigned)LW) s4[t][1] += __ldg(P1 + l1 + 1); else s4[t][1] = -1e30f;
            if ((unsigned)l2 < (unsigned)LW) s4[t][2] += __ldg(P2 + l2); else s4[t][2] = -1e30f;
            if ((unsigned)(l2+1) < (unsigned)LW) s4[t][3] += __ldg(P2 + l2 + 1); else s4[t][3] = -1e30f;
        }

        // ---- online softmax: quad-shfl partials + cross-warp smem combine ----
        float pm1 = -1e30f, pm2 = -1e30f;
#pragma unroll
        for (int t = 0; t < 4; t++) {
            pm1 = fmaxf(pm1, fmaxf(s4[t][0], s4[t][1]));
            pm2 = fmaxf(pm2, fmaxf(s4[t][2], s4[t][3]));
        }
        pm1 = fmaxf(pm1, __shfl_xor_sync(0xffffffffu, pm1, 1));
        pm1 = fmaxf(pm1, __shfl_xor_sync(0xffffffffu, pm1, 2));
        pm2 = fmaxf(pm2, __shfl_xor_sync(0xffffffffu, pm2, 1));
        pm2 = fmaxf(pm2, __shfl_xor_sync(0xffffffffu, pm2, 2));
        if ((lane & 3) == 0) { redm[nh * 64 + r1] = pm1; redm[nh * 64 + r2] = pm2; }
        __syncthreads();
        const float cm1 = fmaxf(redm[r1], redm[64 + r1]);
        const float cm2 = fmaxf(redm[r2], redm[64 + r2]);
        const float mn1 = fmaxf(mr1, cm1), mn2 = fmaxf(mr2, cm2);
        const float corr1 = __expf(mr1 - mn1), corr2 = __expf(mr2 - mn2);
        mr1 = mn1; mr2 = mn2;
        float ps1 = 0.f, ps2 = 0.f;
#pragma unroll
        for (int t = 0; t < 4; t++) {
            const int ct = wns + (t << 3) + ((lane & 3) << 1);
            float e0 = __expf(s4[t][0] - mn1);
            float e1 = __expf(s4[t][1] - mn1);
            float e2 = __expf(s4[t][2] - mn2);
            float e3 = __expf(s4[t][3] - mn2);
            ps1 += e0 + e1;
            ps2 += e2 + e3;
            uint32_t hp, lp;
            split2(e0, e1, hp, lp);
            *(uint32_t*)(smc + AP_H + r1 * 144 + (ct << 1)) = hp;
            *(uint32_t*)(smc + AP_L + r1 * 144 + (ct << 1)) = lp;
            split2(e2, e3, hp, lp);
            *(uint32_t*)(smc + AP_H + r2 * 144 + (ct << 1)) = hp;
            *(uint32_t*)(smc + AP_L + r2 * 144 + (ct << 1)) = lp;
        }
        ps1 += __shfl_xor_sync(0xffffffffu, ps1, 1);
        ps1 += __shfl_xor_sync(0xffffffffu, ps1, 2);
        ps2 += __shfl_xor_sync(0xffffffffu, ps2, 1);
        ps2 += __shfl_xor_sync(0xffffffffu, ps2, 2);
        if ((lane & 3) == 0) { reds[nh * 64 + r1] = ps1; reds[nh * 64 + r2] = ps2; }
        __syncthreads();
        lr1 = lr1 * corr1 + reds[r1] + reds[64 + r1];
        lr2 = lr2 * corr2 + reds[r2] + reds[64 + r2];
#pragma unroll
        for (int t = 0; t < 4; t++) {
            o4[t][0] *= corr1; o4[t][1] *= corr1;
            o4[t][2] *= corr2; o4[t][3] *= corr2;
        }

        // ---- AV: O += P @ V, V^T via ldsm.trans, 3 passes ----
#pragma unroll
        for (int kk = 0; kk < 4; kk++) {
            const uint32_t kb = kk << 5;
            uint32_t ph[4], pl[4];
            {
                uint32_t ar = sb + AP_H + (wm + lrow) * 144 + kb + lcol;
                ldsm_x4(ph[0], ph[1], ph[2], ph[3], ar);
                ldsm_x4(pl[0], pl[1], pl[2], pl[3], ar + (AP_L - AP_H));
            }
            uint32_t bvh[4][2], bvl[4][2];
#pragma unroll
            for (int p = 0; p < 2; p++) {
                uint32_t br = sb + AVS_H + ((kk << 4) + lrow) * 144 + ((wns + (p << 4)) << 1) + lcol;
                uint32_t t0, t1, t2, t3;
                ldsm_x4_t(t0, t1, t2, t3, br);
                bvh[2*p][0] = t0; bvh[2*p][1] = t1;
                bvh[2*p+1][0] = t2; bvh[2*p+1][1] = t3;
                ldsm_x4_t(t0, t1, t2, t3, br + (AVS_L - AVS_H));
                bvl[2*p][0] = t0; bvl[2*p][1] = t1;
                bvl[2*p+1][0] = t2; bvl[2*p+1][1] = t3;
            }
#pragma unroll
            for (int t = 0; t < 4; t++) {
                mma16816(o4[t][0], o4[t][1], o4[t][2], o4[t][3],
                         ph[0], ph[1], ph[2], ph[3], bvh[t][0], bvh[t][1]);
                mma16816(o4[t][0], o4[t][1], o4[t][2], o4[t][3],
                         pl[0], pl[1], pl[2], pl[3], bvh[t][0], bvh[t][1]);
                mma16816(o4[t][0], o4[t][1], o4[t][2], o4[t][3],
                         ph[0], ph[1], ph[2], ph[3], bvl[t][0], bvl[t][1]);
            }
        }
    }

    // ---- epilogue: normalize, write gathered fp32 ----
    const float inv1 = 1.f / lr1;
    const float inv2 = 1.f / lr2;
    const int bb = bh >> 4;
    const int hh = bh & 15;
    const size_t grow1 = (size_t)bb * MQ + m0 + r1;
    const size_t grow2 = (size_t)bb * MQ + m0 + r2;
#pragma unroll
    for (int t = 0; t < 4; t++) {
        const int dt = wns + (t << 3) + ((lane & 3) << 1);
        float2 a = make_float2(o4[t][0] * inv1, o4[t][1] * inv1);
        float2 b = make_float2(o4[t][2] * inv2, o4[t][3] * inv2);
        *(float2*)(gout + grow1 * HID + (hh << 6) + dt) = a;
        *(float2*)(gout + grow2 * HID + (hh << 6) + dt) = b;
    }
}

// =========================================================================
// host launcher
// =========================================================================
extern "C" void kernel_launch(void* const* d_in, const int* in_sizes, int n_in,
                              void* d_out, int out_size)
{
    const float* query  = (const float*)d_in[0];
    const float* key    = (const float*)d_in[1];
    const float* value  = (const float*)d_in[2];
    const float* key_pe = (const float*)d_in[3];
    const float* Wq     = (const float*)d_in[4];
    const float* Wk     = (const float*)d_in[5];
    const float* Wv     = (const float*)d_in[6];
    const float* Wo     = (const float*)d_in[7];
    float* out = (float*)d_out;

    float *pq, *pa, *pP;
    __nv_bfloat16 *kh, *kl, *vh, *vl, *wh, *wl, *peh, *pel;
    cudaGetSymbolAddress((void**)&pq, g_q);
    cudaGetSymbolAddress((void**)&pa, g_attn);
    cudaGetSymbolAddress((void**)&pP, g_P);
    cudaGetSymbolAddress((void**)&kh, g_kh);
    cudaGetSymbolAddress((void**)&kl, g_kl);
    cudaGetSymbolAddress((void**)&vh, g_vh);
    cudaGetSymbolAddress((void**)&vl, g_vl);
    cudaGetSymbolAddress((void**)&wh, g_wh);
    cudaGetSymbolAddress((void**)&wl, g_wl);
    cudaGetSymbolAddress((void**)&peh, g_peh);
    cudaGetSymbolAddress((void**)&pel, g_pel);

    const int nW4 = HID * HID / 4;
    const int wblk = (nW4 + 255) / 256;

    // ---- projections (Q fp32 head-scatter; K/V split-bf16 head-scatter) ----
    split_w<<<wblk, 256>>>(Wq, wh, wl, nW4);
    tc_gemm_mma<<<dim3(8, BB * MQ  / 64), 256>>>(query, wh, wl, pq, nullptr, nullptr,
                                                 HID, HID, HID, MQ,  0.125f, 1);
    split_w<<<wblk, 256>>>(Wk, wh, wl, nW4);
    tc_gemm_mma<<<dim3(8, BB * NKV / 64), 256>>>(key,   wh, wl, nullptr, kh, kl,
                                                 HID, HID, HID, NKV, 1.0f,   2);
    split_w<<<wblk, 256>>>(Wv, wh, wl, nW4);
    tc_gemm_mma<<<dim3(8, BB * NKV / 64), 256>>>(value, wh, wl, nullptr, vh, vl,
                                                 HID, HID, HID, NKV, 1.0f,   2);

    // ---- pe^T pre-split, then grouped pos-bias GEMM + mma attention ----
    split_peT<<<(LW * HD + 255) / 256, 256>>>(key_pe, peh, pel);
    (void)cudaFuncSetAttribute(attn_mma, cudaFuncAttributeMaxDynamicSharedMemorySize, ASMEM);
    for (int g = 0; g < NGRP; g++) {
        const float* qg = pq + (size_t)g * GRP * MQ * HD;
        tc_gemm_mma<<<dim3(LW / 128, GRP * MQ / 64), 256>>>(qg, peh, pel, pP, nullptr, nullptr,
                                                            HD, HD, LW, MQ, 1.0f, 0);
        attn_mma<<<dim3(8, GRP), 256, ASMEM>>>(pq, kh, kl, vh, vl, pP, pa, g * GRP);
    }

    // ---- output projection ----
    split_w<<<wblk, 256>>>(Wo, wh, wl, nW4);
    tc_gemm_mma<<<dim3(8, BB * MQ / 64), 256>>>(pa, wh, wl, out, nullptr, nullptr,
                                                HID, HID, HID, MQ, 1.0f, 0);
}